// round 14
// baseline (speedup 1.0000x reference)
#include <cuda_runtime.h>
#include <cuda_fp16.h>
#include <math.h>

#define Bv    64
#define Pv    196
#define ENCv  2048
#define Ev    512
#define Dv    512
#define Av    512
#define Vv    10000
#define Tv    32
#define NSTEP 31
#define G4D   2048          // 4*D
#define KIN   2560          // ENC + D (ctx | h)
#define KIN_W 2560          // Wih row stride (E+ENC)
#define GZ    4             // gates K-split
#define GCH   640           // KIN / GZ
#define NFCPAD 10112        // fc rows padded to 79*128
#define MEMB  1984          // NSTEP*Bv
#define NBLK  148
#define SMEMB 30720

typedef unsigned long long ull;

// ------------------------- scratch (static device globals) -------------------
__device__ float g_enc_proj[Bv * Pv * Av];        // 25.7 MB
__device__ __half g_eoT[Bv * Pv * ENCv];          // 51.4 MB fp16 transpose [b][p][e]
__device__ __half g_encW16[Av * ENCv];            // 2 MB
__device__ __half g_Wg16[G4D * KIN];              // 10.5 MB  [Wih_ctx | Whh]
__device__ __half g_fcW16[NFCPAD * Dv];           // 10.3 MB
__device__ __half g_decW16[Av * Dv];              // 0.5 MB
__device__ __half g_embA16[2048 * Ev];            // 2 MB gathered emb rows (fp16)
__device__ __half g_Wihe16[G4D * Ev];             // 2 MB Wih embedding slice (fp16)
__device__ __half g_xin16[Bv * KIN];              // fp16 [ctx | h]
__device__ float g_mean[Bv * ENCv];
__device__ float g_h[Bv * Dv];
__device__ float g_c[Bv * Dv];
__device__ float g_dhs[Bv * Av];                  // summed dh (+bias)
__device__ float g_e[Bv * Pv];
__device__ float g_gpart[GZ][Bv * G4D];
__device__ float g_gemb[NSTEP * Bv * G4D];        // 16.2 MB
__device__ unsigned g_bar_count;
__device__ unsigned g_bar_gen;

// ------------------------------- helpers -------------------------------------
__device__ __forceinline__ float wsum(float v) {
#pragma unroll
    for (int o = 16; o; o >>= 1) v += __shfl_down_sync(0xffffffffu, v, o);
    return v;
}
__device__ __forceinline__ float sigm(float x) { return 1.0f / (1.0f + expf(-x)); }

#define MMA_K8(c, a0, a1, b0) \
    asm volatile("mma.sync.aligned.m16n8k8.row.col.f32.f16.f16.f32 " \
                 "{%0,%1,%2,%3}, {%4,%5}, {%6}, {%0,%1,%2,%3};" \
                 : "+f"((c)[0]), "+f"((c)[1]), "+f"((c)[2]), "+f"((c)[3]) \
                 : "r"(a0), "r"(a1), "r"(b0))

// ------------------------ global (grid) barrier --------------------------------
__device__ __forceinline__ void gbar() {
    __threadfence();
    __syncthreads();
    if (threadIdx.x == 0) {
        unsigned gen = *(volatile unsigned*)&g_bar_gen;
        unsigned t = atomicAdd(&g_bar_count, 1u);
        if (t == NBLK - 1) {
            g_bar_count = 0;
            __threadfence();
            *(volatile unsigned*)&g_bar_gen = gen + 1;
        } else {
            while (*(volatile unsigned*)&g_bar_gen == gen) __nanosleep(64);
        }
    }
    __syncthreads();
    __threadfence();
}

// -------------------- zero last timestep + g_mean ------------------------------
__global__ void k_zero_tail(float* __restrict__ preds, float* __restrict__ alphas) {
    int idx = blockIdx.x * blockDim.x + threadIdx.x;
    if (idx < Bv * Vv) {
        int b = idx / Vv, v = idx % Vv;
        preds[((size_t)b * Tv + (Tv - 1)) * Vv + v] = 0.0f;
    } else if (idx < Bv * Vv + Bv * Pv) {
        int r = idx - Bv * Vv;
        int b = r / Pv, p = r % Pv;
        alphas[((size_t)b * Tv + (Tv - 1)) * Pv + p] = 0.0f;
    } else {
        int r = idx - Bv * Vv - Bv * Pv;
        if (r < Bv * ENCv) g_mean[r] = 0.0f;
    }
}

// ------------- transpose eo -> g_eoT fp16 [b][p][e], + mean partials -----------
__global__ void k_cvtT(const float* __restrict__ eo) {
    __shared__ float tile[32][33];
    int b = blockIdx.z;
    int e0 = blockIdx.x * 32;
    int p0 = blockIdx.y * 32;
    int tx = threadIdx.x, ty = threadIdx.y;
#pragma unroll
    for (int r = 0; r < 4; r++) {
        int e = e0 + ty + 8 * r;
        int p = p0 + tx;
        tile[ty + 8 * r][tx] = (p < Pv) ? eo[((size_t)b * ENCv + e) * Pv + p] : 0.0f;
    }
    __syncthreads();
#pragma unroll
    for (int r = 0; r < 4; r++) {
        int p = p0 + ty + 8 * r;
        int e = e0 + tx;
        if (p < Pv)
            g_eoT[((size_t)b * Pv + p) * ENCv + e] = __float2half(tile[tx][ty + 8 * r]);
    }
#pragma unroll
    for (int r = 0; r < 4; r++) {
        float v = wsum(tile[ty + 8 * r][tx]);
        if (tx == 0) atomicAdd(&g_mean[b * ENCv + e0 + ty + 8 * r], v);
    }
}

// -------------------------- fp16 weight converts -------------------------------
__global__ void k_cvtW(const float* __restrict__ W) {
    int i = blockIdx.x * blockDim.x + threadIdx.x;
    const int N4 = Av * ENCv / 4;
    if (i >= N4) return;
    float4 v = ((const float4*)W)[i];
    __half2* out = (__half2*)g_encW16;
    out[i * 2]     = __floats2half2_rn(v.x, v.y);
    out[i * 2 + 1] = __floats2half2_rn(v.z, v.w);
}

__global__ void k_cvt_Wg(const float* __restrict__ Wih, const float* __restrict__ Whh) {
    int i = blockIdx.x * blockDim.x + threadIdx.x;
    const int N2 = G4D * KIN / 2;
    if (i >= N2) return;
    int n = i / (KIN / 2);
    int k = (i % (KIN / 2)) * 2;
    float v0, v1;
    if (k < ENCv) {
        v0 = Wih[(size_t)n * KIN_W + Ev + k];
        v1 = Wih[(size_t)n * KIN_W + Ev + k + 1];
    } else {
        v0 = Whh[(size_t)n * Dv + (k - ENCv)];
        v1 = Whh[(size_t)n * Dv + (k - ENCv) + 1];
    }
    ((__half2*)g_Wg16)[i] = __floats2half2_rn(v0, v1);
}

__global__ void k_cvt_fcW(const float* __restrict__ Wf) {
    int i = blockIdx.x * blockDim.x + threadIdx.x;
    const int N2 = NFCPAD * Dv / 2;
    if (i >= N2) return;
    int n = i / (Dv / 2);
    int k = (i % (Dv / 2)) * 2;
    float v0 = 0.f, v1 = 0.f;
    if (n < Vv) {
        v0 = Wf[(size_t)n * Dv + k];
        v1 = Wf[(size_t)n * Dv + k + 1];
    }
    ((__half2*)g_fcW16)[i] = __floats2half2_rn(v0, v1);
}

__global__ void k_cvt_decW(const float* __restrict__ W) {
    int i = blockIdx.x * blockDim.x + threadIdx.x;
    const int N2 = Av * Dv / 2;
    if (i >= N2) return;
    ((__half2*)g_decW16)[i] = __floats2half2_rn(W[i * 2], W[i * 2 + 1]);
}

__global__ void k_cvt_emb(const int* __restrict__ caps, const float* __restrict__ emb) {
    int i = blockIdx.x * blockDim.x + threadIdx.x;
    const int N2 = 2048 * (Ev / 2);
    if (i >= N2) return;
    int m = i / (Ev / 2);
    int k = (i % (Ev / 2)) * 2;
    float v0 = 0.f, v1 = 0.f;
    if (m < MEMB) {
        int b = m & 63, t = m >> 6;
        int cap = caps[b * Tv + t];
        v0 = emb[(size_t)cap * Ev + k];
        v1 = emb[(size_t)cap * Ev + k + 1];
    }
    ((__half2*)g_embA16)[i] = __floats2half2_rn(v0, v1);
}

__global__ void k_cvt_Wihe(const float* __restrict__ Wih) {
    int i = blockIdx.x * blockDim.x + threadIdx.x;
    const int N2 = G4D * (Ev / 2);
    if (i >= N2) return;
    int n = i / (Ev / 2);
    int k = (i % (Ev / 2)) * 2;
    ((__half2*)g_Wihe16)[i] =
        __floats2half2_rn(Wih[(size_t)n * KIN_W + k], Wih[(size_t)n * KIN_W + k + 1]);
}

// -------------------------------- h0 / c0 -------------------------------------
__global__ void k_init(const float* __restrict__ Wh, const float* __restrict__ bh,
                       const float* __restrict__ Wc, const float* __restrict__ bc) {
    int gw = (blockIdx.x * blockDim.x + threadIdx.x) >> 5;
    int lane = threadIdx.x & 31;
    if (gw >= 2 * Bv * Dv) return;
    int sel = gw >= Bv * Dv;
    int r = gw - sel * Bv * Dv;
    int b = r / Dv, d = r % Dv;
    const float* W = sel ? Wc : Wh;
    const float* mn = g_mean + (size_t)b * ENCv;   // SUMS over p
    const float* wr = W + (size_t)d * ENCv;
    float acc = 0.0f;
    for (int k = lane; k < ENCv; k += 32) acc += mn[k] * wr[k];
    acc = wsum(acc);
    if (!lane) {
        float v = acc * (1.0f / (float)Pv) + (sel ? bc : bh)[d];
        if (sel) g_c[r] = v;
        else { g_h[r] = v; g_xin16[b * KIN + ENCv + d] = __float2half(v); }
    }
}

// -------------------- enc_proj GEMM via HMMA (m16n8k8) -------------------------
__global__ __launch_bounds__(256, 2)
void k_encproj_mma(const float* __restrict__ bias) {
    __shared__ __align__(16) __half As[2][128][40];
    __shared__ __align__(16) __half Bs[2][128][40];
    int m0 = blockIdx.x * 128;
    int n0 = blockIdx.y * 128;
    int tid = threadIdx.x;
    int wid = tid >> 5, lane = tid & 31;
    int wm = wid & 3, wn = wid >> 2;
    int g = lane >> 2, tg = lane & 3;

    int lrow = tid >> 1;
    int lseg = (tid & 1) * 16;

    const __half* Ag = g_eoT + (size_t)(m0 + lrow) * ENCv + lseg;
    const __half* Bg = g_encW16 + (size_t)(n0 + lrow) * ENCv + lseg;

    float c[2][8][4];
#pragma unroll
    for (int mt = 0; mt < 2; mt++)
#pragma unroll
        for (int nt = 0; nt < 8; nt++)
#pragma unroll
            for (int q = 0; q < 4; q++) c[mt][nt][q] = 0.0f;

    *(uint4*)&As[0][lrow][lseg]     = *(const uint4*)(Ag);
    *(uint4*)&As[0][lrow][lseg + 8] = *(const uint4*)(Ag + 8);
    *(uint4*)&Bs[0][lrow][lseg]     = *(const uint4*)(Bg);
    *(uint4*)&Bs[0][lrow][lseg + 8] = *(const uint4*)(Bg + 8);
    __syncthreads();

    int buf = 0;
    for (int k0 = 0; k0 < ENCv; k0 += 32) {
        uint4 pa0, pa1, pb0, pb1;
        bool more = (k0 + 32 < ENCv);
        if (more) {
            pa0 = *(const uint4*)(Ag + k0 + 32);
            pa1 = *(const uint4*)(Ag + k0 + 40);
            pb0 = *(const uint4*)(Bg + k0 + 32);
            pb1 = *(const uint4*)(Bg + k0 + 40);
        }
#pragma unroll
        for (int ks = 0; ks < 4; ks++) {
            int kk = ks * 8 + tg * 2;
            unsigned a0[2], a1[2];
#pragma unroll
            for (int mt = 0; mt < 2; mt++) {
                int row = wm * 32 + mt * 16;
                a0[mt] = *(const unsigned*)&As[buf][row + g][kk];
                a1[mt] = *(const unsigned*)&As[buf][row + 8 + g][kk];
            }
#pragma unroll
            for (int nt = 0; nt < 8; nt++) {
                unsigned b0 = *(const unsigned*)&Bs[buf][wn * 64 + nt * 8 + g][kk];
#pragma unroll
                for (int mt = 0; mt < 2; mt++) MMA_K8(c[mt][nt], a0[mt], a1[mt], b0);
            }
        }
        if (more) {
            *(uint4*)&As[buf ^ 1][lrow][lseg]     = pa0;
            *(uint4*)&As[buf ^ 1][lrow][lseg + 8] = pa1;
            *(uint4*)&Bs[buf ^ 1][lrow][lseg]     = pb0;
            *(uint4*)&Bs[buf ^ 1][lrow][lseg + 8] = pb1;
        }
        __syncthreads();
        buf ^= 1;
    }

#pragma unroll
    for (int nt = 0; nt < 8; nt++) {
        int n = n0 + wn * 64 + nt * 8 + tg * 2;
        float b0f = bias[n], b1f = bias[n + 1];
#pragma unroll
        for (int mt = 0; mt < 2; mt++) {
            int m = m0 + wm * 32 + mt * 16 + g;
            *(float2*)&g_enc_proj[(size_t)m * Av + n] =
                make_float2(c[mt][nt][0] + b0f, c[mt][nt][1] + b1f);
            *(float2*)&g_enc_proj[(size_t)(m + 8) * Av + n] =
                make_float2(c[mt][nt][2] + b0f, c[mt][nt][3] + b1f);
        }
    }
}

// ------------------ g_gemb = embA @ Wihe.T via HMMA ----------------------------
__global__ __launch_bounds__(256, 2)
void k_embW_mma() {
    __shared__ __align__(16) __half As[2][128][40];
    __shared__ __align__(16) __half Bs[2][128][40];
    int m0 = blockIdx.x * 128;
    int n0 = blockIdx.y * 128;
    int tid = threadIdx.x;
    int wid = tid >> 5, lane = tid & 31;
    int wm = wid & 3, wn = wid >> 2;
    int g = lane >> 2, tg = lane & 3;

    int lrow = tid >> 1;
    int lseg = (tid & 1) * 16;

    const __half* Ag = g_embA16 + (size_t)(m0 + lrow) * Ev + lseg;
    const __half* Bg = g_Wihe16 + (size_t)(n0 + lrow) * Ev + lseg;

    float c[2][8][4];
#pragma unroll
    for (int mt = 0; mt < 2; mt++)
#pragma unroll
        for (int nt = 0; nt < 8; nt++)
#pragma unroll
            for (int q = 0; q < 4; q++) c[mt][nt][q] = 0.0f;

    *(uint4*)&As[0][lrow][lseg]     = *(const uint4*)(Ag);
    *(uint4*)&As[0][lrow][lseg + 8] = *(const uint4*)(Ag + 8);
    *(uint4*)&Bs[0][lrow][lseg]     = *(const uint4*)(Bg);
    *(uint4*)&Bs[0][lrow][lseg + 8] = *(const uint4*)(Bg + 8);
    __syncthreads();

    int buf = 0;
    for (int k0 = 0; k0 < Ev; k0 += 32) {
        uint4 pa0, pa1, pb0, pb1;
        bool more = (k0 + 32 < Ev);
        if (more) {
            pa0 = *(const uint4*)(Ag + k0 + 32);
            pa1 = *(const uint4*)(Ag + k0 + 40);
            pb0 = *(const uint4*)(Bg + k0 + 32);
            pb1 = *(const uint4*)(Bg + k0 + 40);
        }
#pragma unroll
        for (int ks = 0; ks < 4; ks++) {
            int kk = ks * 8 + tg * 2;
            unsigned a0[2], a1[2];
#pragma unroll
            for (int mt = 0; mt < 2; mt++) {
                int row = wm * 32 + mt * 16;
                a0[mt] = *(const unsigned*)&As[buf][row + g][kk];
                a1[mt] = *(const unsigned*)&As[buf][row + 8 + g][kk];
            }
#pragma unroll
            for (int nt = 0; nt < 8; nt++) {
                unsigned b0 = *(const unsigned*)&Bs[buf][wn * 64 + nt * 8 + g][kk];
#pragma unroll
                for (int mt = 0; mt < 2; mt++) MMA_K8(c[mt][nt], a0[mt], a1[mt], b0);
            }
        }
        if (more) {
            *(uint4*)&As[buf ^ 1][lrow][lseg]     = pa0;
            *(uint4*)&As[buf ^ 1][lrow][lseg + 8] = pa1;
            *(uint4*)&Bs[buf ^ 1][lrow][lseg]     = pb0;
            *(uint4*)&Bs[buf ^ 1][lrow][lseg + 8] = pb1;
        }
        __syncthreads();
        buf ^= 1;
    }

#pragma unroll
    for (int nt = 0; nt < 8; nt++) {
        int n = n0 + wn * 64 + nt * 8 + tg * 2;
#pragma unroll
        for (int mt = 0; mt < 2; mt++) {
            int m = m0 + wm * 32 + mt * 16 + g;
            if (m < MEMB)
                *(float2*)&g_gemb[(size_t)m * G4D + n] =
                    make_float2(c[mt][nt][0], c[mt][nt][1]);
            if (m + 8 < MEMB)
                *(float2*)&g_gemb[(size_t)(m + 8) * G4D + n] =
                    make_float2(c[mt][nt][2], c[mt][nt][3]);
        }
    }
}

// ------------- M=64, K=512 fp16 MMA against h-slice of xin ----------------------
__device__ __forceinline__ void mma_h512(char* s_raw, int n0, const __half* Bmat,
                                         const float* bias, float* preds, int t,
                                         bool to_preds) {
    __half (*As)[64][40]  = (__half(*)[64][40])s_raw;
    __half (*Bs)[128][40] = (__half(*)[128][40])(s_raw + 10240);
    int tid = threadIdx.x;
    int wid = tid >> 5, lane = tid & 31;
    int wm = wid & 1, wn = wid >> 1;
    int g = lane >> 2, tg = lane & 3;

    int arow = tid >> 2;
    int aseg = (tid & 3) * 8;
    int brow = tid >> 1;
    int bseg = (tid & 1) * 16;

    const __half* Ag = g_xin16 + (size_t)arow * KIN + ENCv + aseg;
    const __half* Bg = Bmat + (size_t)(n0 + brow) * Dv + bseg;

    float c[2][4][4];
#pragma unroll
    for (int mt = 0; mt < 2; mt++)
#pragma unroll
        for (int nt = 0; nt < 4; nt++)
#pragma unroll
            for (int q = 0; q < 4; q++) c[mt][nt][q] = 0.0f;

    *(uint4*)&(*As)[arow][aseg]      = *(const uint4*)(Ag);
    *(uint4*)&(*Bs)[brow][bseg]      = *(const uint4*)(Bg);
    *(uint4*)&(*Bs)[brow][bseg + 8]  = *(const uint4*)(Bg + 8);
    __syncthreads();

    int buf = 0;
    for (int k0 = 0; k0 < Dv; k0 += 32) {
        uint4 pa, pb0, pb1;
        bool more = (k0 + 32 < Dv);
        if (more) {
            pa  = *(const uint4*)(Ag + k0 + 32);
            pb0 = *(const uint4*)(Bg + k0 + 32);
            pb1 = *(const uint4*)(Bg + k0 + 40);
        }
#pragma unroll
        for (int ks = 0; ks < 4; ks++) {
            int kk = ks * 8 + tg * 2;
            unsigned a0[2], a1[2];
#pragma unroll
            for (int mt = 0; mt < 2; mt++) {
                int row = wm * 32 + mt * 16;
                a0[mt] = *(const unsigned*)&As[buf][row + g][kk];
                a1[mt] = *(const unsigned*)&As[buf][row + 8 + g][kk];
            }
#pragma unroll
            for (int nt = 0; nt < 4; nt++) {
                unsigned b0 = *(const unsigned*)&Bs[buf][wn * 32 + nt * 8 + g][kk];
#pragma unroll
                for (int mt = 0; mt < 2; mt++) MMA_K8(c[mt][nt], a0[mt], a1[mt], b0);
            }
        }
        if (more) {
            *(uint4*)&As[buf ^ 1][arow][aseg]     = pa;
            *(uint4*)&Bs[buf ^ 1][brow][bseg]     = pb0;
            *(uint4*)&Bs[buf ^ 1][brow][bseg + 8] = pb1;
        }
        __syncthreads();
        buf ^= 1;
    }

#pragma unroll
    for (int nt = 0; nt < 4; nt++) {
        int n = n0 + wn * 32 + nt * 8 + tg * 2;
        if (to_preds && n >= Vv) continue;
        float b0f = bias[n], b1f = bias[n + 1];
#pragma unroll
        for (int mt = 0; mt < 2; mt++) {
            int m = wm * 32 + mt * 16 + g;
            if (to_preds) {
                *(float2*)&preds[((size_t)m * Tv + t) * Vv + n] =
                    make_float2(c[mt][nt][0] + b0f, c[mt][nt][1] + b1f);
                *(float2*)&preds[((size_t)(m + 8) * Tv + t) * Vv + n] =
                    make_float2(c[mt][nt][2] + b0f, c[mt][nt][3] + b1f);
            } else {
                *(float2*)&g_dhs[m * Av + n] =
                    make_float2(c[mt][nt][0] + b0f, c[mt][nt][1] + b1f);
                *(float2*)&g_dhs[(m + 8) * Av + n] =
                    make_float2(c[mt][nt][2] + b0f, c[mt][nt][3] + b1f);
            }
        }
    }
}

// ---------------------- gates MMA phase body ------------------------------------
__device__ __forceinline__ void gates_task(char* s_raw, int n0, int z) {
    __half (*As)[64][40]  = (__half(*)[64][40])s_raw;
    __half (*Bs)[128][40] = (__half(*)[128][40])(s_raw + 10240);
    int kbase = z * GCH;
    int tid = threadIdx.x;
    int wid = tid >> 5, lane = tid & 31;
    int wm = wid & 1, wn = wid >> 1;
    int g = lane >> 2, tg = lane & 3;

    int arow = tid >> 2;
    int aseg = (tid & 3) * 8;
    int brow = tid >> 1;
    int bseg = (tid & 1) * 16;

    const __half* Ag = g_xin16 + (size_t)arow * KIN + kbase + aseg;
    const __half* Bg = g_Wg16 + (size_t)(n0 + brow) * KIN + kbase + bseg;

    float c[2][4][4];
#pragma unroll
    for (int mt = 0; mt < 2; mt++)
#pragma unroll
        for (int nt = 0; nt < 4; nt++)
#pragma unroll
            for (int q = 0; q < 4; q++) c[mt][nt][q] = 0.0f;

    *(uint4*)&(*As)[arow][aseg]     = *(const uint4*)(Ag);
    *(uint4*)&(*Bs)[brow][bseg]     = *(const uint4*)(Bg);
    *(uint4*)&(*Bs)[brow][bseg + 8] = *(const uint4*)(Bg + 8);
    __syncthreads();

    int buf = 0;
    for (int k0 = 0; k0 < GCH; k0 += 32) {
        uint4 pa, pb0, pb1;
        bool more = (k0 + 32 < GCH);
        if (more) {
            pa  = *(const uint4*)(Ag + k0 + 32);
            pb0 = *(const uint4*)(Bg + k0 + 32);
            pb1 = *(const uint4*)(Bg + k0 + 40);
        }
#pragma unroll
        for (int ks = 0; ks < 4; ks++) {
            int kk = ks * 8 + tg * 2;
            unsigned a0[2], a1[2];
#pragma unroll
            for (int mt = 0; mt < 2; mt++) {
                int row = wm * 32 + mt * 16;
                a0[mt] = *(const unsigned*)&As[buf][row + g][kk];
                a1[mt] = *(const unsigned*)&As[buf][row + 8 + g][kk];
            }
#pragma unroll
            for (int nt = 0; nt < 4; nt++) {
                unsigned b0 = *(const unsigned*)&Bs[buf][wn * 32 + nt * 8 + g][kk];
#pragma unroll
                for (int mt = 0; mt < 2; mt++) MMA_K8(c[mt][nt], a0[mt], a1[mt], b0);
            }
        }
        if (more) {
            *(uint4*)&As[buf ^ 1][arow][aseg]     = pa;
            *(uint4*)&Bs[buf ^ 1][brow][bseg]     = pb0;
            *(uint4*)&Bs[buf ^ 1][brow][bseg + 8] = pb1;
        }
        __syncthreads();
        buf ^= 1;
    }

#pragma unroll
    for (int nt = 0; nt < 4; nt++) {
        int n = n0 + wn * 32 + nt * 8 + tg * 2;
#pragma unroll
        for (int mt = 0; mt < 2; mt++) {
            int m = wm * 32 + mt * 16 + g;
            *(float2*)&g_gpart[z][m * G4D + n] = make_float2(c[mt][nt][0], c[mt][nt][1]);
            *(float2*)&g_gpart[z][(m + 8) * G4D + n] = make_float2(c[mt][nt][2], c[mt][nt][3]);
        }
    }
}

// ------------------- persistent loop kernel ------------------------------------
__global__ __launch_bounds__(256, 1)
void k_loop(const float* __restrict__ fullW, const float* __restrict__ fullb,
            const float* __restrict__ bih, const float* __restrict__ bhh,
            const float* __restrict__ decb, const float* __restrict__ fcb,
            float* __restrict__ preds, float* __restrict__ alphas) {
    extern __shared__ __align__(16) char s_raw[];
    int bid = blockIdx.x;
    int tid = threadIdx.x;
    int wid = tid >> 5, lane = tid & 31;
    float fullb0 = fullb[0];

    // ---- P0: dh(h0) — required before t=0's attention ----
    if (bid < 4) mma_h512(s_raw, bid * 128, g_decW16, decb, nullptr, 0, false);
    gbar();

    for (int t = 0; t < NSTEP; t++) {
        // ---- P1: e scores (blocks 0..99) | fc(t-1) (blocks 100..147) ----
        if (bid < 100) {
            int gw = bid * 8 + wid;
            for (int task = gw; task < Bv * Pv; task += 800) {
                int b = task / Pv;
                const float* ep = g_enc_proj + (size_t)task * Av;
                const float* dh = g_dhs + b * Av;
                float acc = 0.0f;
#pragma unroll
                for (int k = lane; k < Av; k += 32) {
                    float v = ep[k] + dh[k];
                    acc += fmaxf(v, 0.0f) * fullW[k];
                }
                acc = wsum(acc);
                if (!lane) g_e[task] = acc + fullb0;
            }
        } else if (t > 0) {
            for (int task = bid - 100; task < 79; task += 48)
                mma_h512(s_raw, task * 128, g_fcW16, fcb, preds, t - 1, true);
        }
        gbar();

        // ---- P2: softmax (redundant) + context, 256 tasks ----
        {
            float* red  = (float*)s_raw;
            float* s_al = red + 256;
            for (int task = bid; task < 256; task += NBLK) {
                __syncthreads();
                int b = task >> 2;
                int quarter = task & 3;
                float v = (tid < Pv) ? g_e[b * Pv + tid] : -3.0e38f;
                red[tid] = v; __syncthreads();
                for (int s = 128; s; s >>= 1) {
                    if (tid < s) red[tid] = fmaxf(red[tid], red[tid + s]);
                    __syncthreads();
                }
                float mx = red[0]; __syncthreads();
                float ex = (tid < Pv) ? expf(v - mx) : 0.0f;
                red[tid] = ex; __syncthreads();
                for (int s = 128; s; s >>= 1) {
                    if (tid < s) red[tid] += red[tid + s];
                    __syncthreads();
                }
                float inv = 1.0f / red[0];
                if (tid < Pv) {
                    float al = ex * inv;
                    s_al[tid] = al;
                    if (quarter == 0)
                        alphas[((size_t)b * Tv + t) * Pv + tid] = al;
                }
                __syncthreads();

                int c = quarter * 256 + tid;   // half2 column
                const __half2* base2 = (const __half2*)(g_eoT + (size_t)b * Pv * ENCv);
                float ax = 0.f, ay = 0.f;
#pragma unroll 4
                for (int p = 0; p < Pv; p++) {
                    float al = s_al[p];
                    float2 x = __half22float2(base2[(size_t)p * (ENCv / 2) + c]);
                    ax += al * x.x; ay += al * x.y;
                }
                ((__half2*)(g_xin16 + (size_t)b * KIN))[c] = __floats2half2_rn(ax, ay);
            }
        }
        gbar();

        // ---- P3: gates MMA, 64 tasks ----
        if (bid < 64) gates_task(s_raw, (bid & 15) * 128, bid >> 4);
        gbar();

        // ---- P4: LSTM pointwise ----
        {
            int idx = bid * 256 + tid;
            if (idx < Bv * Dv) {
                int b = idx / Dv, d = idx % Dv;
                const float* ge = g_gemb + ((size_t)t * Bv + b) * G4D;
                float gi = bih[d] + bhh[d] + ge[d];
                float gf = bih[Dv + d] + bhh[Dv + d] + ge[Dv + d];
                float gg = bih[2 * Dv + d] + bhh[2 * Dv + d] + ge[2 * Dv + d];
                float go = bih[3 * Dv + d] + bhh[3 * Dv + d] + ge[3 * Dv + d];
                int base = b * G4D + d;
#pragma unroll
                for (int z = 0; z < GZ; z++) {
                    gi += g_gpart[z][base];
                    gf += g_gpart[z][base + Dv];
                    gg += g_gpart[z][base + 2 * Dv];
                    go += g_gpart[z][base + 3 * Dv];
                }
                float c = g_c[idx];
                float cn = sigm(gf) * c + sigm(gi) * tanhf(gg);
                float hn = sigm(go) * tanhf(cn);
                g_c[idx] = cn;
                g_h[idx] = hn;
                g_xin16[b * KIN + ENCv + d] = __float2half(hn);
            }
        }
        gbar();

        // ---- P5: dh MMA for next step, 4 tasks ----
        if (bid < 4) mma_h512(s_raw, bid * 128, g_decW16, decb, nullptr, 0, false);
        gbar();
    }

    // final fc for t = NSTEP-1
    if (bid < 79)
        mma_h512(s_raw, bid * 128, g_fcW16, fcb, preds, NSTEP - 1, true);
}

// --------------------------------- launcher ------------------------------------
extern "C" void kernel_launch(void* const* d_in, const int* in_sizes, int n_in,
                              void* d_out, int out_size) {
    const float* eo    = (const float*)d_in[0];
    const int*   caps  = (const int*)d_in[1];
    const float* emb   = (const float*)d_in[3];
    const float* encW  = (const float*)d_in[4];
    const float* encb  = (const float*)d_in[5];
    const float* decW  = (const float*)d_in[6];
    const float* decb  = (const float*)d_in[7];
    const float* fullW = (const float*)d_in[8];
    const float* fullb = (const float*)d_in[9];
    const float* ihW   = (const float*)d_in[10];
    const float* ihb   = (const float*)d_in[11];
    const float* icW   = (const float*)d_in[12];
    const float* icb   = (const float*)d_in[13];
    const float* Wih   = (const float*)d_in[14];
    const float* bih   = (const float*)d_in[15];
    const float* Whh   = (const float*)d_in[16];
    const float* bhh   = (const float*)d_in[17];
    const float* fcW   = (const float*)d_in[18];
    const float* fcb   = (const float*)d_in[19];

    float* preds  = (float*)d_out;
    float* alphas = preds + (size_t)Bv * Tv * Vv;

    k_zero_tail<<<(Bv * Vv + Bv * Pv + Bv * ENCv + 255) / 256, 256>>>(preds, alphas);
    k_cvtT<<<dim3(ENCv / 32, (Pv + 31) / 32, Bv), dim3(32, 8)>>>(eo);
    k_cvtW<<<(Av * ENCv / 4 + 255) / 256, 256>>>(encW);
    k_cvt_Wg<<<(G4D * KIN / 2 + 255) / 256, 256>>>(Wih, Whh);
    k_cvt_fcW<<<(NFCPAD * Dv / 2 + 255) / 256, 256>>>(fcW);
    k_cvt_decW<<<(Av * Dv / 2 + 255) / 256, 256>>>(decW);
    k_cvt_emb<<<(2048 * Ev / 2 + 255) / 256, 256>>>(caps, emb);
    k_cvt_Wihe<<<(G4D * Ev / 2 + 255) / 256, 256>>>(Wih);
    k_init<<<(2 * Bv * Dv * 32 + 255) / 256, 256>>>(ihW, ihb, icW, icb);
    k_embW_mma<<<dim3(16, 16), 256>>>();
    k_encproj_mma<<<dim3(98, 4), 256>>>(encb);
    k_loop<<<NBLK, 256, SMEMB>>>(fullW, fullb, bih, bhh, decb, fcb, preds, alphas);
}

// round 15
// speedup vs baseline: 1.7050x; 1.7050x over previous
#include <cuda_runtime.h>
#include <cuda_fp16.h>
#include <math.h>

#define Bv    64
#define Pv    196
#define ENCv  2048
#define Ev    512
#define Dv    512
#define Av    512
#define Vv    10000
#define Tv    32
#define NSTEP 31
#define G4D   2048          // 4*D
#define KIN   2560          // ENC + D (ctx | h)
#define KIN_W 2560          // Wih row stride (E+ENC)
#define GZ    4             // gates K-split
#define GCH   640           // KIN / GZ
#define NFCPAD 10112        // fc rows padded to 79*128
#define MEMB  1984          // NSTEP*Bv

typedef unsigned long long ull;

// ------------------------- scratch (static device globals) -------------------
__device__ float g_enc_proj[Bv * Pv * Av];        // 25.7 MB
__device__ __half g_eoT[Bv * Pv * ENCv];          // 51.4 MB fp16 transpose [b][p][e]
__device__ __half g_encW16[Av * ENCv];            // 2 MB
__device__ __half g_Wg16[G4D * KIN];              // 10.5 MB  [Wih_ctx | Whh]
__device__ __half g_fcW16[NFCPAD * Dv];           // 10.3 MB
__device__ __half g_decW16[Av * Dv];              // 0.5 MB
__device__ __half g_embA16[2048 * Ev];            // 2 MB gathered emb rows (fp16)
__device__ __half g_Wihe16[G4D * Ev];             // 2 MB Wih embedding slice (fp16)
__device__ __half g_xin16[Bv * KIN];              // fp16 [ctx | h]
__device__ __half g_hall16[2048 * Dv];            // 2 MB fp16 h history [t*64+b][d]
__device__ float g_mean[Bv * ENCv];
__device__ float g_h[Bv * Dv];
__device__ float g_c[Bv * Dv];
__device__ float g_dhs[Bv * Av];                  // summed dh (+bias)
__device__ float g_e[Bv * Pv];
__device__ float g_gpart[GZ][Bv * G4D];
__device__ float g_gemb[NSTEP * Bv * G4D];        // 16.2 MB

// ------------------------------- helpers -------------------------------------
__device__ __forceinline__ float wsum(float v) {
#pragma unroll
    for (int o = 16; o; o >>= 1) v += __shfl_down_sync(0xffffffffu, v, o);
    return v;
}
__device__ __forceinline__ float sigm(float x) { return 1.0f / (1.0f + expf(-x)); }

#define MMA_K8(c, a0, a1, b0) \
    asm volatile("mma.sync.aligned.m16n8k8.row.col.f32.f16.f16.f32 " \
                 "{%0,%1,%2,%3}, {%4,%5}, {%6}, {%0,%1,%2,%3};" \
                 : "+f"((c)[0]), "+f"((c)[1]), "+f"((c)[2]), "+f"((c)[3]) \
                 : "r"(a0), "r"(a1), "r"(b0))

// -------------------- zero last timestep + g_mean ------------------------------
__global__ void k_zero_tail(float* __restrict__ preds, float* __restrict__ alphas) {
    int idx = blockIdx.x * blockDim.x + threadIdx.x;
    if (idx < Bv * Vv) {
        int b = idx / Vv, v = idx % Vv;
        preds[((size_t)b * Tv + (Tv - 1)) * Vv + v] = 0.0f;
    } else if (idx < Bv * Vv + Bv * Pv) {
        int r = idx - Bv * Vv;
        int b = r / Pv, p = r % Pv;
        alphas[((size_t)b * Tv + (Tv - 1)) * Pv + p] = 0.0f;
    } else {
        int r = idx - Bv * Vv - Bv * Pv;
        if (r < Bv * ENCv) g_mean[r] = 0.0f;
    }
}

// ------------- transpose eo -> g_eoT fp16 [b][p][e], + mean partials -----------
__global__ void k_cvtT(const float* __restrict__ eo) {
    __shared__ float tile[32][33];
    int b = blockIdx.z;
    int e0 = blockIdx.x * 32;
    int p0 = blockIdx.y * 32;
    int tx = threadIdx.x, ty = threadIdx.y;
#pragma unroll
    for (int r = 0; r < 4; r++) {
        int e = e0 + ty + 8 * r;
        int p = p0 + tx;
        tile[ty + 8 * r][tx] = (p < Pv) ? eo[((size_t)b * ENCv + e) * Pv + p] : 0.0f;
    }
    __syncthreads();
#pragma unroll
    for (int r = 0; r < 4; r++) {
        int p = p0 + ty + 8 * r;
        int e = e0 + tx;
        if (p < Pv)
            g_eoT[((size_t)b * Pv + p) * ENCv + e] = __float2half(tile[tx][ty + 8 * r]);
    }
#pragma unroll
    for (int r = 0; r < 4; r++) {
        float v = wsum(tile[ty + 8 * r][tx]);
        if (tx == 0) atomicAdd(&g_mean[b * ENCv + e0 + ty + 8 * r], v);
    }
}

// -------------------------- fp16 weight converts -------------------------------
__global__ void k_cvtW(const float* __restrict__ W) {
    int i = blockIdx.x * blockDim.x + threadIdx.x;
    const int N4 = Av * ENCv / 4;
    if (i >= N4) return;
    float4 v = ((const float4*)W)[i];
    __half2* out = (__half2*)g_encW16;
    out[i * 2]     = __floats2half2_rn(v.x, v.y);
    out[i * 2 + 1] = __floats2half2_rn(v.z, v.w);
}

__global__ void k_cvt_Wg(const float* __restrict__ Wih, const float* __restrict__ Whh) {
    int i = blockIdx.x * blockDim.x + threadIdx.x;
    const int N2 = G4D * KIN / 2;
    if (i >= N2) return;
    int n = i / (KIN / 2);
    int k = (i % (KIN / 2)) * 2;
    float v0, v1;
    if (k < ENCv) {
        v0 = Wih[(size_t)n * KIN_W + Ev + k];
        v1 = Wih[(size_t)n * KIN_W + Ev + k + 1];
    } else {
        v0 = Whh[(size_t)n * Dv + (k - ENCv)];
        v1 = Whh[(size_t)n * Dv + (k - ENCv) + 1];
    }
    ((__half2*)g_Wg16)[i] = __floats2half2_rn(v0, v1);
}

__global__ void k_cvt_fcW(const float* __restrict__ Wf) {
    int i = blockIdx.x * blockDim.x + threadIdx.x;
    const int N2 = NFCPAD * Dv / 2;
    if (i >= N2) return;
    int n = i / (Dv / 2);
    int k = (i % (Dv / 2)) * 2;
    float v0 = 0.f, v1 = 0.f;
    if (n < Vv) {
        v0 = Wf[(size_t)n * Dv + k];
        v1 = Wf[(size_t)n * Dv + k + 1];
    }
    ((__half2*)g_fcW16)[i] = __floats2half2_rn(v0, v1);
}

__global__ void k_cvt_decW(const float* __restrict__ W) {
    int i = blockIdx.x * blockDim.x + threadIdx.x;
    const int N2 = Av * Dv / 2;
    if (i >= N2) return;
    ((__half2*)g_decW16)[i] = __floats2half2_rn(W[i * 2], W[i * 2 + 1]);
}

__global__ void k_cvt_emb(const int* __restrict__ caps, const float* __restrict__ emb) {
    int i = blockIdx.x * blockDim.x + threadIdx.x;
    const int N2 = 2048 * (Ev / 2);
    if (i >= N2) return;
    int m = i / (Ev / 2);
    int k = (i % (Ev / 2)) * 2;
    float v0 = 0.f, v1 = 0.f;
    if (m < MEMB) {
        int b = m & 63, t = m >> 6;
        int cap = caps[b * Tv + t];
        v0 = emb[(size_t)cap * Ev + k];
        v1 = emb[(size_t)cap * Ev + k + 1];
    }
    ((__half2*)g_embA16)[i] = __floats2half2_rn(v0, v1);
}

__global__ void k_cvt_Wihe(const float* __restrict__ Wih) {
    int i = blockIdx.x * blockDim.x + threadIdx.x;
    const int N2 = G4D * (Ev / 2);
    if (i >= N2) return;
    int n = i / (Ev / 2);
    int k = (i % (Ev / 2)) * 2;
    ((__half2*)g_Wihe16)[i] =
        __floats2half2_rn(Wih[(size_t)n * KIN_W + k], Wih[(size_t)n * KIN_W + k + 1]);
}

// -------------------------------- h0 / c0 -------------------------------------
__global__ void k_init(const float* __restrict__ Wh, const float* __restrict__ bh,
                       const float* __restrict__ Wc, const float* __restrict__ bc) {
    int gw = (blockIdx.x * blockDim.x + threadIdx.x) >> 5;
    int lane = threadIdx.x & 31;
    if (gw >= 2 * Bv * Dv) return;
    int sel = gw >= Bv * Dv;
    int r = gw - sel * Bv * Dv;
    int b = r / Dv, d = r % Dv;
    const float* W = sel ? Wc : Wh;
    const float* mn = g_mean + (size_t)b * ENCv;   // SUMS over p
    const float* wr = W + (size_t)d * ENCv;
    float acc = 0.0f;
    for (int k = lane; k < ENCv; k += 32) acc += mn[k] * wr[k];
    acc = wsum(acc);
    if (!lane) {
        float v = acc * (1.0f / (float)Pv) + (sel ? bc : bh)[d];
        if (sel) g_c[r] = v;
        else { g_h[r] = v; g_xin16[b * KIN + ENCv + d] = __float2half(v); }
    }
}

// -------------------- enc_proj GEMM via HMMA (m16n8k8) -------------------------
__global__ __launch_bounds__(256, 2)
void k_encproj_mma(const float* __restrict__ bias) {
    __shared__ __align__(16) __half As[2][128][40];
    __shared__ __align__(16) __half Bs[2][128][40];
    int m0 = blockIdx.x * 128;
    int n0 = blockIdx.y * 128;
    int tid = threadIdx.x;
    int wid = tid >> 5, lane = tid & 31;
    int wm = wid & 3, wn = wid >> 2;
    int g = lane >> 2, tg = lane & 3;

    int lrow = tid >> 1;
    int lseg = (tid & 1) * 16;

    const __half* Ag = g_eoT + (size_t)(m0 + lrow) * ENCv + lseg;
    const __half* Bg = g_encW16 + (size_t)(n0 + lrow) * ENCv + lseg;

    float c[2][8][4];
#pragma unroll
    for (int mt = 0; mt < 2; mt++)
#pragma unroll
        for (int nt = 0; nt < 8; nt++)
#pragma unroll
            for (int q = 0; q < 4; q++) c[mt][nt][q] = 0.0f;

    *(uint4*)&As[0][lrow][lseg]     = *(const uint4*)(Ag);
    *(uint4*)&As[0][lrow][lseg + 8] = *(const uint4*)(Ag + 8);
    *(uint4*)&Bs[0][lrow][lseg]     = *(const uint4*)(Bg);
    *(uint4*)&Bs[0][lrow][lseg + 8] = *(const uint4*)(Bg + 8);
    __syncthreads();

    int buf = 0;
    for (int k0 = 0; k0 < ENCv; k0 += 32) {
        uint4 pa0, pa1, pb0, pb1;
        bool more = (k0 + 32 < ENCv);
        if (more) {
            pa0 = *(const uint4*)(Ag + k0 + 32);
            pa1 = *(const uint4*)(Ag + k0 + 40);
            pb0 = *(const uint4*)(Bg + k0 + 32);
            pb1 = *(const uint4*)(Bg + k0 + 40);
        }
#pragma unroll
        for (int ks = 0; ks < 4; ks++) {
            int kk = ks * 8 + tg * 2;
            unsigned a0[2], a1[2];
#pragma unroll
            for (int mt = 0; mt < 2; mt++) {
                int row = wm * 32 + mt * 16;
                a0[mt] = *(const unsigned*)&As[buf][row + g][kk];
                a1[mt] = *(const unsigned*)&As[buf][row + 8 + g][kk];
            }
#pragma unroll
            for (int nt = 0; nt < 8; nt++) {
                unsigned b0 = *(const unsigned*)&Bs[buf][wn * 64 + nt * 8 + g][kk];
#pragma unroll
                for (int mt = 0; mt < 2; mt++) MMA_K8(c[mt][nt], a0[mt], a1[mt], b0);
            }
        }
        if (more) {
            *(uint4*)&As[buf ^ 1][lrow][lseg]     = pa0;
            *(uint4*)&As[buf ^ 1][lrow][lseg + 8] = pa1;
            *(uint4*)&Bs[buf ^ 1][lrow][lseg]     = pb0;
            *(uint4*)&Bs[buf ^ 1][lrow][lseg + 8] = pb1;
        }
        __syncthreads();
        buf ^= 1;
    }

#pragma unroll
    for (int nt = 0; nt < 8; nt++) {
        int n = n0 + wn * 64 + nt * 8 + tg * 2;
        float b0f = bias[n], b1f = bias[n + 1];
#pragma unroll
        for (int mt = 0; mt < 2; mt++) {
            int m = m0 + wm * 32 + mt * 16 + g;
            *(float2*)&g_enc_proj[(size_t)m * Av + n] =
                make_float2(c[mt][nt][0] + b0f, c[mt][nt][1] + b1f);
            *(float2*)&g_enc_proj[(size_t)(m + 8) * Av + n] =
                make_float2(c[mt][nt][2] + b0f, c[mt][nt][3] + b1f);
        }
    }
}

// ------------------ g_gemb = embA @ Wihe.T via HMMA ----------------------------
__global__ __launch_bounds__(256, 2)
void k_embW_mma() {
    __shared__ __align__(16) __half As[2][128][40];
    __shared__ __align__(16) __half Bs[2][128][40];
    int m0 = blockIdx.x * 128;
    int n0 = blockIdx.y * 128;
    int tid = threadIdx.x;
    int wid = tid >> 5, lane = tid & 31;
    int wm = wid & 3, wn = wid >> 2;
    int g = lane >> 2, tg = lane & 3;

    int lrow = tid >> 1;
    int lseg = (tid & 1) * 16;

    const __half* Ag = g_embA16 + (size_t)(m0 + lrow) * Ev + lseg;
    const __half* Bg = g_Wihe16 + (size_t)(n0 + lrow) * Ev + lseg;

    float c[2][8][4];
#pragma unroll
    for (int mt = 0; mt < 2; mt++)
#pragma unroll
        for (int nt = 0; nt < 8; nt++)
#pragma unroll
            for (int q = 0; q < 4; q++) c[mt][nt][q] = 0.0f;

    *(uint4*)&As[0][lrow][lseg]     = *(const uint4*)(Ag);
    *(uint4*)&As[0][lrow][lseg + 8] = *(const uint4*)(Ag + 8);
    *(uint4*)&Bs[0][lrow][lseg]     = *(const uint4*)(Bg);
    *(uint4*)&Bs[0][lrow][lseg + 8] = *(const uint4*)(Bg + 8);
    __syncthreads();

    int buf = 0;
    for (int k0 = 0; k0 < Ev; k0 += 32) {
        uint4 pa0, pa1, pb0, pb1;
        bool more = (k0 + 32 < Ev);
        if (more) {
            pa0 = *(const uint4*)(Ag + k0 + 32);
            pa1 = *(const uint4*)(Ag + k0 + 40);
            pb0 = *(const uint4*)(Bg + k0 + 32);
            pb1 = *(const uint4*)(Bg + k0 + 40);
        }
#pragma unroll
        for (int ks = 0; ks < 4; ks++) {
            int kk = ks * 8 + tg * 2;
            unsigned a0[2], a1[2];
#pragma unroll
            for (int mt = 0; mt < 2; mt++) {
                int row = wm * 32 + mt * 16;
                a0[mt] = *(const unsigned*)&As[buf][row + g][kk];
                a1[mt] = *(const unsigned*)&As[buf][row + 8 + g][kk];
            }
#pragma unroll
            for (int nt = 0; nt < 8; nt++) {
                unsigned b0 = *(const unsigned*)&Bs[buf][wn * 64 + nt * 8 + g][kk];
#pragma unroll
                for (int mt = 0; mt < 2; mt++) MMA_K8(c[mt][nt], a0[mt], a1[mt], b0);
            }
        }
        if (more) {
            *(uint4*)&As[buf ^ 1][lrow][lseg]     = pa0;
            *(uint4*)&As[buf ^ 1][lrow][lseg + 8] = pa1;
            *(uint4*)&Bs[buf ^ 1][lrow][lseg]     = pb0;
            *(uint4*)&Bs[buf ^ 1][lrow][lseg + 8] = pb1;
        }
        __syncthreads();
        buf ^= 1;
    }

#pragma unroll
    for (int nt = 0; nt < 8; nt++) {
        int n = n0 + wn * 64 + nt * 8 + tg * 2;
#pragma unroll
        for (int mt = 0; mt < 2; mt++) {
            int m = m0 + wm * 32 + mt * 16 + g;
            if (m < MEMB)
                *(float2*)&g_gemb[(size_t)m * G4D + n] =
                    make_float2(c[mt][nt][0], c[mt][nt][1]);
            if (m + 8 < MEMB)
                *(float2*)&g_gemb[(size_t)(m + 8) * G4D + n] =
                    make_float2(c[mt][nt][2], c[mt][nt][3]);
        }
    }
}

// ----------------- final batched fc: preds = hall @ fcW.T ----------------------
// A = g_hall16 [2048][512], B = g_fcW16 [10112][512]; grid (16, 79)
__global__ __launch_bounds__(256, 2)
void k_fc_all(const float* __restrict__ bf, float* __restrict__ preds) {
    __shared__ __align__(16) __half As[2][128][40];
    __shared__ __align__(16) __half Bs[2][128][40];
    int m0 = blockIdx.x * 128;
    int n0 = blockIdx.y * 128;
    int tid = threadIdx.x;
    int wid = tid >> 5, lane = tid & 31;
    int wm = wid & 3, wn = wid >> 2;
    int g = lane >> 2, tg = lane & 3;

    int lrow = tid >> 1;
    int lseg = (tid & 1) * 16;

    const __half* Ag = g_hall16 + (size_t)(m0 + lrow) * Dv + lseg;
    const __half* Bg = g_fcW16 + (size_t)(n0 + lrow) * Dv + lseg;

    float c[2][8][4];
#pragma unroll
    for (int mt = 0; mt < 2; mt++)
#pragma unroll
        for (int nt = 0; nt < 8; nt++)
#pragma unroll
            for (int q = 0; q < 4; q++) c[mt][nt][q] = 0.0f;

    *(uint4*)&As[0][lrow][lseg]     = *(const uint4*)(Ag);
    *(uint4*)&As[0][lrow][lseg + 8] = *(const uint4*)(Ag + 8);
    *(uint4*)&Bs[0][lrow][lseg]     = *(const uint4*)(Bg);
    *(uint4*)&Bs[0][lrow][lseg + 8] = *(const uint4*)(Bg + 8);
    __syncthreads();

    int buf = 0;
    for (int k0 = 0; k0 < Dv; k0 += 32) {
        uint4 pa0, pa1, pb0, pb1;
        bool more = (k0 + 32 < Dv);
        if (more) {
            pa0 = *(const uint4*)(Ag + k0 + 32);
            pa1 = *(const uint4*)(Ag + k0 + 40);
            pb0 = *(const uint4*)(Bg + k0 + 32);
            pb1 = *(const uint4*)(Bg + k0 + 40);
        }
#pragma unroll
        for (int ks = 0; ks < 4; ks++) {
            int kk = ks * 8 + tg * 2;
            unsigned a0[2], a1[2];
#pragma unroll
            for (int mt = 0; mt < 2; mt++) {
                int row = wm * 32 + mt * 16;
                a0[mt] = *(const unsigned*)&As[buf][row + g][kk];
                a1[mt] = *(const unsigned*)&As[buf][row + 8 + g][kk];
            }
#pragma unroll
            for (int nt = 0; nt < 8; nt++) {
                unsigned b0 = *(const unsigned*)&Bs[buf][wn * 64 + nt * 8 + g][kk];
#pragma unroll
                for (int mt = 0; mt < 2; mt++) MMA_K8(c[mt][nt], a0[mt], a1[mt], b0);
            }
        }
        if (more) {
            *(uint4*)&As[buf ^ 1][lrow][lseg]     = pa0;
            *(uint4*)&As[buf ^ 1][lrow][lseg + 8] = pa1;
            *(uint4*)&Bs[buf ^ 1][lrow][lseg]     = pb0;
            *(uint4*)&Bs[buf ^ 1][lrow][lseg + 8] = pb1;
        }
        __syncthreads();
        buf ^= 1;
    }

#pragma unroll
    for (int nt = 0; nt < 8; nt++) {
        int n = n0 + wn * 64 + nt * 8 + tg * 2;
        if (n >= Vv) continue;
        float b0f = bf[n], b1f = bf[n + 1];
#pragma unroll
        for (int mt = 0; mt < 2; mt++) {
            int m = m0 + wm * 32 + mt * 16 + g;
            if (m < MEMB) {
                int b = m & 63, t = m >> 6;
                *(float2*)&preds[((size_t)b * Tv + t) * Vv + n] =
                    make_float2(c[mt][nt][0] + b0f, c[mt][nt][1] + b1f);
            }
            int m2 = m + 8;
            if (m2 < MEMB) {
                int b = m2 & 63, t = m2 >> 6;
                *(float2*)&preds[((size_t)b * Tv + t) * Vv + n] =
                    make_float2(c[mt][nt][2] + b0f, c[mt][nt][3] + b1f);
            }
        }
    }
}

// ------------- dh: M=64, K=512 fp16 MMA -> g_dhs (+decb); 4 blocks -------------
__global__ void k_dh16(const float* __restrict__ decb) {
    __shared__ __align__(16) __half As[2][64][40];
    __shared__ __align__(16) __half Bs[2][128][40];
    int n0 = blockIdx.x * 128;
    int tid = threadIdx.x;
    int wid = tid >> 5, lane = tid & 31;
    int wm = wid & 1, wn = wid >> 1;
    int g = lane >> 2, tg = lane & 3;

    int arow = tid >> 2;
    int aseg = (tid & 3) * 8;
    int brow = tid >> 1;
    int bseg = (tid & 1) * 16;

    const __half* Ag = g_xin16 + (size_t)arow * KIN + ENCv + aseg;
    const __half* Bg = g_decW16 + (size_t)(n0 + brow) * Dv + bseg;

    float c[2][4][4];
#pragma unroll
    for (int mt = 0; mt < 2; mt++)
#pragma unroll
        for (int nt = 0; nt < 4; nt++)
#pragma unroll
            for (int q = 0; q < 4; q++) c[mt][nt][q] = 0.0f;

    *(uint4*)&As[0][arow][aseg]     = *(const uint4*)(Ag);
    *(uint4*)&Bs[0][brow][bseg]     = *(const uint4*)(Bg);
    *(uint4*)&Bs[0][brow][bseg + 8] = *(const uint4*)(Bg + 8);
    __syncthreads();

    int buf = 0;
    for (int k0 = 0; k0 < Dv; k0 += 32) {
        uint4 pa, pb0, pb1;
        bool more = (k0 + 32 < Dv);
        if (more) {
            pa  = *(const uint4*)(Ag + k0 + 32);
            pb0 = *(const uint4*)(Bg + k0 + 32);
            pb1 = *(const uint4*)(Bg + k0 + 40);
        }
#pragma unroll
        for (int ks = 0; ks < 4; ks++) {
            int kk = ks * 8 + tg * 2;
            unsigned a0[2], a1[2];
#pragma unroll
            for (int mt = 0; mt < 2; mt++) {
                int row = wm * 32 + mt * 16;
                a0[mt] = *(const unsigned*)&As[buf][row + g][kk];
                a1[mt] = *(const unsigned*)&As[buf][row + 8 + g][kk];
            }
#pragma unroll
            for (int nt = 0; nt < 4; nt++) {
                unsigned b0 = *(const unsigned*)&Bs[buf][wn * 32 + nt * 8 + g][kk];
#pragma unroll
                for (int mt = 0; mt < 2; mt++) MMA_K8(c[mt][nt], a0[mt], a1[mt], b0);
            }
        }
        if (more) {
            *(uint4*)&As[buf ^ 1][arow][aseg]     = pa;
            *(uint4*)&Bs[buf ^ 1][brow][bseg]     = pb0;
            *(uint4*)&Bs[buf ^ 1][brow][bseg + 8] = pb1;
        }
        __syncthreads();
        buf ^= 1;
    }

#pragma unroll
    for (int nt = 0; nt < 4; nt++) {
        int n = n0 + wn * 32 + nt * 8 + tg * 2;
        float b0f = decb[n], b1f = decb[n + 1];
#pragma unroll
        for (int mt = 0; mt < 2; mt++) {
            int m = wm * 32 + mt * 16 + g;
            *(float2*)&g_dhs[m * Av + n] =
                make_float2(c[mt][nt][0] + b0f, c[mt][nt][1] + b1f);
            *(float2*)&g_dhs[(m + 8) * Av + n] =
                make_float2(c[mt][nt][2] + b0f, c[mt][nt][3] + b1f);
        }
    }
}

// ----------------------- e scores: grid (25, 64) -------------------------------
__global__ void k_e(const float* __restrict__ fullW, const float* __restrict__ fullb) {
    __shared__ float s_dh[Av];
    __shared__ float s_fw[Av];
    int b = blockIdx.y;
    int tid = threadIdx.x;
    for (int i = tid; i < Av; i += 256) {
        s_dh[i] = g_dhs[b * Av + i];
        s_fw[i] = fullW[i];
    }
    __syncthreads();
    int w = tid >> 5, lane = tid & 31;
    int p = blockIdx.x * 8 + w;
    if (p >= Pv) return;
    const float* ep = g_enc_proj + (size_t)(b * Pv + p) * Av;
    float acc = 0.0f;
#pragma unroll
    for (int k = lane; k < Av; k += 32) {
        float v = ep[k] + s_dh[k];
        acc += fmaxf(v, 0.0f) * s_fw[k];
    }
    acc = wsum(acc);
    if (!lane) g_e[b * Pv + p] = acc + fullb[0];
}

// ------------- softmax (redundant) + context: grid (4, 64) ---------------------
__global__ void k_ctx(float* __restrict__ out_alphas, int t) {
    __shared__ float red[256];
    __shared__ float s_al[Pv];
    int b = blockIdx.y;
    int tid = threadIdx.x;

    float v = (tid < Pv) ? g_e[b * Pv + tid] : -3.0e38f;
    red[tid] = v; __syncthreads();
    for (int s = 128; s; s >>= 1) {
        if (tid < s) red[tid] = fmaxf(red[tid], red[tid + s]);
        __syncthreads();
    }
    float mx = red[0]; __syncthreads();
    float ex = (tid < Pv) ? expf(v - mx) : 0.0f;
    red[tid] = ex; __syncthreads();
    for (int s = 128; s; s >>= 1) {
        if (tid < s) red[tid] += red[tid + s];
        __syncthreads();
    }
    float inv = 1.0f / red[0];
    if (tid < Pv) {
        float al = ex * inv;
        s_al[tid] = al;
        if (blockIdx.x == 0)
            out_alphas[((size_t)b * Tv + t) * Pv + tid] = al;
    }
    __syncthreads();

    int c = blockIdx.x * 256 + tid;   // half2 column
    const __half2* base2 = (const __half2*)(g_eoT + (size_t)b * Pv * ENCv);
    float ax = 0.f, ay = 0.f;
#pragma unroll 4
    for (int p = 0; p < Pv; p++) {
        float al = s_al[p];
        float2 x = __half22float2(base2[(size_t)p * (ENCv / 2) + c]);
        ax += al * x.x; ay += al * x.y;
    }
    ((__half2*)(g_xin16 + (size_t)b * KIN))[c] = __floats2half2_rn(ax, ay);
}

// ------------------- gates GEMM via HMMA, K-split 4 -----------------------------
__global__ void k_gates_mma() {
    __shared__ __align__(16) __half As[2][64][40];
    __shared__ __align__(16) __half Bs[2][128][40];
    int n0 = blockIdx.x * 128;
    int z = blockIdx.y;
    int kbase = z * GCH;
    int tid = threadIdx.x;
    int wid = tid >> 5, lane = tid & 31;
    int wm = wid & 1, wn = wid >> 1;
    int g = lane >> 2, tg = lane & 3;

    int arow = tid >> 2;
    int aseg = (tid & 3) * 8;
    int brow = tid >> 1;
    int bseg = (tid & 1) * 16;

    const __half* Ag = g_xin16 + (size_t)arow * KIN + kbase + aseg;
    const __half* Bg = g_Wg16 + (size_t)(n0 + brow) * KIN + kbase + bseg;

    float c[2][4][4];
#pragma unroll
    for (int mt = 0; mt < 2; mt++)
#pragma unroll
        for (int nt = 0; nt < 4; nt++)
#pragma unroll
            for (int q = 0; q < 4; q++) c[mt][nt][q] = 0.0f;

    *(uint4*)&As[0][arow][aseg]     = *(const uint4*)(Ag);
    *(uint4*)&Bs[0][brow][bseg]     = *(const uint4*)(Bg);
    *(uint4*)&Bs[0][brow][bseg + 8] = *(const uint4*)(Bg + 8);
    __syncthreads();

    int buf = 0;
    for (int k0 = 0; k0 < GCH; k0 += 32) {
        uint4 pa, pb0, pb1;
        bool more = (k0 + 32 < GCH);
        if (more) {
            pa  = *(const uint4*)(Ag + k0 + 32);
            pb0 = *(const uint4*)(Bg + k0 + 32);
            pb1 = *(const uint4*)(Bg + k0 + 40);
        }
#pragma unroll
        for (int ks = 0; ks < 4; ks++) {
            int kk = ks * 8 + tg * 2;
            unsigned a0[2], a1[2];
#pragma unroll
            for (int mt = 0; mt < 2; mt++) {
                int row = wm * 32 + mt * 16;
                a0[mt] = *(const unsigned*)&As[buf][row + g][kk];
                a1[mt] = *(const unsigned*)&As[buf][row + 8 + g][kk];
            }
#pragma unroll
            for (int nt = 0; nt < 4; nt++) {
                unsigned b0 = *(const unsigned*)&Bs[buf][wn * 32 + nt * 8 + g][kk];
#pragma unroll
                for (int mt = 0; mt < 2; mt++) MMA_K8(c[mt][nt], a0[mt], a1[mt], b0);
            }
        }
        if (more) {
            *(uint4*)&As[buf ^ 1][arow][aseg]     = pa;
            *(uint4*)&Bs[buf ^ 1][brow][bseg]     = pb0;
            *(uint4*)&Bs[buf ^ 1][brow][bseg + 8] = pb1;
        }
        __syncthreads();
        buf ^= 1;
    }

#pragma unroll
    for (int nt = 0; nt < 4; nt++) {
        int n = n0 + wn * 32 + nt * 8 + tg * 2;
#pragma unroll
        for (int mt = 0; mt < 2; mt++) {
            int m = wm * 32 + mt * 16 + g;
            *(float2*)&g_gpart[z][m * G4D + n] = make_float2(c[mt][nt][0], c[mt][nt][1]);
            *(float2*)&g_gpart[z][(m + 8) * G4D + n] = make_float2(c[mt][nt][2], c[mt][nt][3]);
        }
    }
}

// ------------------------------ LSTM pointwise ---------------------------------
__global__ void k_lstm(const float* __restrict__ bih, const float* __restrict__ bhh, int t) {
    int idx = blockIdx.x * blockDim.x + threadIdx.x;
    if (idx >= Bv * Dv) return;
    int b = idx / Dv, d = idx % Dv;
    const float* ge = g_gemb + ((size_t)t * Bv + b) * G4D;
    float gi = bih[d] + bhh[d] + ge[d];
    float gf = bih[Dv + d] + bhh[Dv + d] + ge[Dv + d];
    float gg = bih[2 * Dv + d] + bhh[2 * Dv + d] + ge[2 * Dv + d];
    float go = bih[3 * Dv + d] + bhh[3 * Dv + d] + ge[3 * Dv + d];
    int base = b * G4D + d;
#pragma unroll
    for (int z = 0; z < GZ; z++) {
        gi += g_gpart[z][base];
        gf += g_gpart[z][base + Dv];
        gg += g_gpart[z][base + 2 * Dv];
        go += g_gpart[z][base + 3 * Dv];
    }
    float c = g_c[idx];
    float cn = sigm(gf) * c + sigm(gi) * tanhf(gg);
    float hn = sigm(go) * tanhf(cn);
    g_c[idx] = cn;
    g_h[idx] = hn;
    __half h16 = __float2half(hn);
    g_xin16[b * KIN + ENCv + d] = h16;
    g_hall16[((size_t)t * Bv + b) * Dv + d] = h16;   // history for batched fc
}

// --------------------------------- launcher ------------------------------------
extern "C" void kernel_launch(void* const* d_in, const int* in_sizes, int n_in,
                              void* d_out, int out_size) {
    const float* eo    = (const float*)d_in[0];
    const int*   caps  = (const int*)d_in[1];
    const float* emb   = (const float*)d_in[3];
    const float* encW  = (const float*)d_in[4];
    const float* encb  = (const float*)d_in[5];
    const float* decW  = (const float*)d_in[6];
    const float* decb  = (const float*)d_in[7];
    const float* fullW = (const float*)d_in[8];
    const float* fullb = (const float*)d_in[9];
    const float* ihW   = (const float*)d_in[10];
    const float* ihb   = (const float*)d_in[11];
    const float* icW   = (const float*)d_in[12];
    const float* icb   = (const float*)d_in[13];
    const float* Wih   = (const float*)d_in[14];
    const float* bih   = (const float*)d_in[15];
    const float* Whh   = (const float*)d_in[16];
    const float* bhh   = (const float*)d_in[17];
    const float* fcW   = (const float*)d_in[18];
    const float* fcb   = (const float*)d_in[19];

    float* preds  = (float*)d_out;
    float* alphas = preds + (size_t)Bv * Tv * Vv;

    k_zero_tail<<<(Bv * Vv + Bv * Pv + Bv * ENCv + 255) / 256, 256>>>(preds, alphas);
    k_cvtT<<<dim3(ENCv / 32, (Pv + 31) / 32, Bv), dim3(32, 8)>>>(eo);
    k_cvtW<<<(Av * ENCv / 4 + 255) / 256, 256>>>(encW);
    k_cvt_Wg<<<(G4D * KIN / 2 + 255) / 256, 256>>>(Wih, Whh);
    k_cvt_fcW<<<(NFCPAD * Dv / 2 + 255) / 256, 256>>>(fcW);
    k_cvt_decW<<<(Av * Dv / 2 + 255) / 256, 256>>>(decW);
    k_cvt_emb<<<(2048 * Ev / 2 + 255) / 256, 256>>>(caps, emb);
    k_cvt_Wihe<<<(G4D * Ev / 2 + 255) / 256, 256>>>(Wih);
    k_init<<<(2 * Bv * Dv * 32 + 255) / 256, 256>>>(ihW, ihb, icW, icb);
    k_embW_mma<<<dim3(16, 16), 256>>>();
    k_encproj_mma<<<dim3(98, 4), 256>>>(encb);
    k_dh16<<<4, 256>>>(decb);

    for (int t = 0; t < NSTEP; t++) {
        k_e<<<dim3(25, Bv), 256>>>(fullW, fullb);
        k_ctx<<<dim3(4, Bv), 256>>>(alphas, t);
        k_gates_mma<<<dim3(16, GZ), 256>>>();
        k_lstm<<<(Bv * Dv + 255) / 256, 256>>>(bih, bhh, t);
        if (t + 1 < NSTEP) k_dh16<<<4, 256>>>(decb);
    }
    k_fc_all<<<dim3(16, 79), 256>>>(fcb, preds);
}

// round 16
// speedup vs baseline: 1.7116x; 1.0039x over previous
#include <cuda_runtime.h>
#include <cuda_fp16.h>
#include <math.h>

#define Bv    64
#define Pv    196
#define ENCv  2048
#define Ev    512
#define Dv    512
#define Av    512
#define Vv    10000
#define Tv    32
#define NSTEP 31
#define G4D   2048          // 4*D
#define KIN   2560          // ENC + D (ctx | h)
#define KIN_W 2560          // Wih row stride (E+ENC)
#define GZ    4             // gates K-split
#define GCH   640           // KIN / GZ
#define NFCPAD 10112        // fc rows padded to 79*128
#define MEMB  1984          // NSTEP*Bv

typedef unsigned long long ull;

// ------------------------- scratch (static device globals) -------------------
__device__ float g_enc_proj[Bv * Pv * Av];        // 25.7 MB
__device__ __half g_eoT[Bv * Pv * ENCv];          // 51.4 MB fp16 transpose [b][p][e]
__device__ __half g_encW16[Av * ENCv];            // 2 MB
__device__ __half g_Wg16[G4D * KIN];              // 10.5 MB  [Wih_ctx | Whh]
__device__ __half g_fcW16[NFCPAD * Dv];           // 10.3 MB
__device__ __half g_decW16[Av * Dv];              // 0.5 MB
__device__ __half g_embA16[2048 * Ev];            // 2 MB gathered emb rows (fp16)
__device__ __half g_Wihe16[G4D * Ev];             // 2 MB Wih embedding slice (fp16)
__device__ __half g_xin16[Bv * KIN];              // fp16 [ctx | h]
__device__ __half g_hall16[2048 * Dv];            // 2 MB fp16 h history [t*64+b][d]
__device__ float g_mean[Bv * ENCv];
__device__ float g_h[Bv * Dv];
__device__ float g_c[Bv * Dv];
__device__ float g_dhs[Bv * Av];                  // summed dh (+bias)
__device__ float g_e[Bv * Pv];
__device__ float g_gpart[GZ][Bv * G4D];
__device__ float g_gemb[NSTEP * Bv * G4D];        // 16.2 MB

// ------------------------------- helpers -------------------------------------
__device__ __forceinline__ float wsum(float v) {
#pragma unroll
    for (int o = 16; o; o >>= 1) v += __shfl_down_sync(0xffffffffu, v, o);
    return v;
}
__device__ __forceinline__ float sigm(float x) { return 1.0f / (1.0f + expf(-x)); }

#define MMA_K8(c, a0, a1, b0) \
    asm volatile("mma.sync.aligned.m16n8k8.row.col.f32.f16.f16.f32 " \
                 "{%0,%1,%2,%3}, {%4,%5}, {%6}, {%0,%1,%2,%3};" \
                 : "+f"((c)[0]), "+f"((c)[1]), "+f"((c)[2]), "+f"((c)[3]) \
                 : "r"(a0), "r"(a1), "r"(b0))

// -------------------- zero last timestep + g_mean ------------------------------
__global__ void k_zero_tail(float* __restrict__ preds, float* __restrict__ alphas) {
    int idx = blockIdx.x * blockDim.x + threadIdx.x;
    if (idx < Bv * Vv) {
        int b = idx / Vv, v = idx % Vv;
        preds[((size_t)b * Tv + (Tv - 1)) * Vv + v] = 0.0f;
    } else if (idx < Bv * Vv + Bv * Pv) {
        int r = idx - Bv * Vv;
        int b = r / Pv, p = r % Pv;
        alphas[((size_t)b * Tv + (Tv - 1)) * Pv + p] = 0.0f;
    } else {
        int r = idx - Bv * Vv - Bv * Pv;
        if (r < Bv * ENCv) g_mean[r] = 0.0f;
    }
}

// ------------- transpose eo -> g_eoT fp16 [b][p][e], + mean partials -----------
__global__ void k_cvtT(const float* __restrict__ eo) {
    __shared__ float tile[32][33];
    int b = blockIdx.z;
    int e0 = blockIdx.x * 32;
    int p0 = blockIdx.y * 32;
    int tx = threadIdx.x, ty = threadIdx.y;
#pragma unroll
    for (int r = 0; r < 4; r++) {
        int e = e0 + ty + 8 * r;
        int p = p0 + tx;
        tile[ty + 8 * r][tx] = (p < Pv) ? eo[((size_t)b * ENCv + e) * Pv + p] : 0.0f;
    }
    __syncthreads();
#pragma unroll
    for (int r = 0; r < 4; r++) {
        int p = p0 + ty + 8 * r;
        int e = e0 + tx;
        if (p < Pv)
            g_eoT[((size_t)b * Pv + p) * ENCv + e] = __float2half(tile[tx][ty + 8 * r]);
    }
#pragma unroll
    for (int r = 0; r < 4; r++) {
        float v = wsum(tile[ty + 8 * r][tx]);
        if (tx == 0) atomicAdd(&g_mean[b * ENCv + e0 + ty + 8 * r], v);
    }
}

// -------------------------- fp16 weight converts -------------------------------
__global__ void k_cvtW(const float* __restrict__ W) {
    int i = blockIdx.x * blockDim.x + threadIdx.x;
    const int N4 = Av * ENCv / 4;
    if (i >= N4) return;
    float4 v = ((const float4*)W)[i];
    __half2* out = (__half2*)g_encW16;
    out[i * 2]     = __floats2half2_rn(v.x, v.y);
    out[i * 2 + 1] = __floats2half2_rn(v.z, v.w);
}

__global__ void k_cvt_Wg(const float* __restrict__ Wih, const float* __restrict__ Whh) {
    int i = blockIdx.x * blockDim.x + threadIdx.x;
    const int N2 = G4D * KIN / 2;
    if (i >= N2) return;
    int n = i / (KIN / 2);
    int k = (i % (KIN / 2)) * 2;
    float v0, v1;
    if (k < ENCv) {
        v0 = Wih[(size_t)n * KIN_W + Ev + k];
        v1 = Wih[(size_t)n * KIN_W + Ev + k + 1];
    } else {
        v0 = Whh[(size_t)n * Dv + (k - ENCv)];
        v1 = Whh[(size_t)n * Dv + (k - ENCv) + 1];
    }
    ((__half2*)g_Wg16)[i] = __floats2half2_rn(v0, v1);
}

__global__ void k_cvt_fcW(const float* __restrict__ Wf) {
    int i = blockIdx.x * blockDim.x + threadIdx.x;
    const int N2 = NFCPAD * Dv / 2;
    if (i >= N2) return;
    int n = i / (Dv / 2);
    int k = (i % (Dv / 2)) * 2;
    float v0 = 0.f, v1 = 0.f;
    if (n < Vv) {
        v0 = Wf[(size_t)n * Dv + k];
        v1 = Wf[(size_t)n * Dv + k + 1];
    }
    ((__half2*)g_fcW16)[i] = __floats2half2_rn(v0, v1);
}

__global__ void k_cvt_decW(const float* __restrict__ W) {
    int i = blockIdx.x * blockDim.x + threadIdx.x;
    const int N2 = Av * Dv / 2;
    if (i >= N2) return;
    ((__half2*)g_decW16)[i] = __floats2half2_rn(W[i * 2], W[i * 2 + 1]);
}

__global__ void k_cvt_emb(const int* __restrict__ caps, const float* __restrict__ emb) {
    int i = blockIdx.x * blockDim.x + threadIdx.x;
    const int N2 = 2048 * (Ev / 2);
    if (i >= N2) return;
    int m = i / (Ev / 2);
    int k = (i % (Ev / 2)) * 2;
    float v0 = 0.f, v1 = 0.f;
    if (m < MEMB) {
        int b = m & 63, t = m >> 6;
        int cap = caps[b * Tv + t];
        v0 = emb[(size_t)cap * Ev + k];
        v1 = emb[(size_t)cap * Ev + k + 1];
    }
    ((__half2*)g_embA16)[i] = __floats2half2_rn(v0, v1);
}

__global__ void k_cvt_Wihe(const float* __restrict__ Wih) {
    int i = blockIdx.x * blockDim.x + threadIdx.x;
    const int N2 = G4D * (Ev / 2);
    if (i >= N2) return;
    int n = i / (Ev / 2);
    int k = (i % (Ev / 2)) * 2;
    ((__half2*)g_Wihe16)[i] =
        __floats2half2_rn(Wih[(size_t)n * KIN_W + k], Wih[(size_t)n * KIN_W + k + 1]);
}

// -------------------------------- h0 / c0 -------------------------------------
__global__ void k_init(const float* __restrict__ Wh, const float* __restrict__ bh,
                       const float* __restrict__ Wc, const float* __restrict__ bc) {
    int gw = (blockIdx.x * blockDim.x + threadIdx.x) >> 5;
    int lane = threadIdx.x & 31;
    if (gw >= 2 * Bv * Dv) return;
    int sel = gw >= Bv * Dv;
    int r = gw - sel * Bv * Dv;
    int b = r / Dv, d = r % Dv;
    const float* W = sel ? Wc : Wh;
    const float* mn = g_mean + (size_t)b * ENCv;   // SUMS over p
    const float* wr = W + (size_t)d * ENCv;
    float acc = 0.0f;
    for (int k = lane; k < ENCv; k += 32) acc += mn[k] * wr[k];
    acc = wsum(acc);
    if (!lane) {
        float v = acc * (1.0f / (float)Pv) + (sel ? bc : bh)[d];
        if (sel) g_c[r] = v;
        else { g_h[r] = v; g_xin16[b * KIN + ENCv + d] = __float2half(v); }
    }
}

// -------------------- enc_proj GEMM via HMMA (m16n8k8) -------------------------
__global__ __launch_bounds__(256, 2)
void k_encproj_mma(const float* __restrict__ bias) {
    __shared__ __align__(16) __half As[2][128][40];
    __shared__ __align__(16) __half Bs[2][128][40];
    int m0 = blockIdx.x * 128;
    int n0 = blockIdx.y * 128;
    int tid = threadIdx.x;
    int wid = tid >> 5, lane = tid & 31;
    int wm = wid & 3, wn = wid >> 2;
    int g = lane >> 2, tg = lane & 3;

    int lrow = tid >> 1;
    int lseg = (tid & 1) * 16;

    const __half* Ag = g_eoT + (size_t)(m0 + lrow) * ENCv + lseg;
    const __half* Bg = g_encW16 + (size_t)(n0 + lrow) * ENCv + lseg;

    float c[2][8][4];
#pragma unroll
    for (int mt = 0; mt < 2; mt++)
#pragma unroll
        for (int nt = 0; nt < 8; nt++)
#pragma unroll
            for (int q = 0; q < 4; q++) c[mt][nt][q] = 0.0f;

    *(uint4*)&As[0][lrow][lseg]     = *(const uint4*)(Ag);
    *(uint4*)&As[0][lrow][lseg + 8] = *(const uint4*)(Ag + 8);
    *(uint4*)&Bs[0][lrow][lseg]     = *(const uint4*)(Bg);
    *(uint4*)&Bs[0][lrow][lseg + 8] = *(const uint4*)(Bg + 8);
    __syncthreads();

    int buf = 0;
    for (int k0 = 0; k0 < ENCv; k0 += 32) {
        uint4 pa0, pa1, pb0, pb1;
        bool more = (k0 + 32 < ENCv);
        if (more) {
            pa0 = *(const uint4*)(Ag + k0 + 32);
            pa1 = *(const uint4*)(Ag + k0 + 40);
            pb0 = *(const uint4*)(Bg + k0 + 32);
            pb1 = *(const uint4*)(Bg + k0 + 40);
        }
#pragma unroll
        for (int ks = 0; ks < 4; ks++) {
            int kk = ks * 8 + tg * 2;
            unsigned a0[2], a1[2];
#pragma unroll
            for (int mt = 0; mt < 2; mt++) {
                int row = wm * 32 + mt * 16;
                a0[mt] = *(const unsigned*)&As[buf][row + g][kk];
                a1[mt] = *(const unsigned*)&As[buf][row + 8 + g][kk];
            }
#pragma unroll
            for (int nt = 0; nt < 8; nt++) {
                unsigned b0 = *(const unsigned*)&Bs[buf][wn * 64 + nt * 8 + g][kk];
#pragma unroll
                for (int mt = 0; mt < 2; mt++) MMA_K8(c[mt][nt], a0[mt], a1[mt], b0);
            }
        }
        if (more) {
            *(uint4*)&As[buf ^ 1][lrow][lseg]     = pa0;
            *(uint4*)&As[buf ^ 1][lrow][lseg + 8] = pa1;
            *(uint4*)&Bs[buf ^ 1][lrow][lseg]     = pb0;
            *(uint4*)&Bs[buf ^ 1][lrow][lseg + 8] = pb1;
        }
        __syncthreads();
        buf ^= 1;
    }

#pragma unroll
    for (int nt = 0; nt < 8; nt++) {
        int n = n0 + wn * 64 + nt * 8 + tg * 2;
        float b0f = bias[n], b1f = bias[n + 1];
#pragma unroll
        for (int mt = 0; mt < 2; mt++) {
            int m = m0 + wm * 32 + mt * 16 + g;
            *(float2*)&g_enc_proj[(size_t)m * Av + n] =
                make_float2(c[mt][nt][0] + b0f, c[mt][nt][1] + b1f);
            *(float2*)&g_enc_proj[(size_t)(m + 8) * Av + n] =
                make_float2(c[mt][nt][2] + b0f, c[mt][nt][3] + b1f);
        }
    }
}

// ------------------ g_gemb = embA @ Wihe.T via HMMA ----------------------------
__global__ __launch_bounds__(256, 2)
void k_embW_mma() {
    __shared__ __align__(16) __half As[2][128][40];
    __shared__ __align__(16) __half Bs[2][128][40];
    int m0 = blockIdx.x * 128;
    int n0 = blockIdx.y * 128;
    int tid = threadIdx.x;
    int wid = tid >> 5, lane = tid & 31;
    int wm = wid & 3, wn = wid >> 2;
    int g = lane >> 2, tg = lane & 3;

    int lrow = tid >> 1;
    int lseg = (tid & 1) * 16;

    const __half* Ag = g_embA16 + (size_t)(m0 + lrow) * Ev + lseg;
    const __half* Bg = g_Wihe16 + (size_t)(n0 + lrow) * Ev + lseg;

    float c[2][8][4];
#pragma unroll
    for (int mt = 0; mt < 2; mt++)
#pragma unroll
        for (int nt = 0; nt < 8; nt++)
#pragma unroll
            for (int q = 0; q < 4; q++) c[mt][nt][q] = 0.0f;

    *(uint4*)&As[0][lrow][lseg]     = *(const uint4*)(Ag);
    *(uint4*)&As[0][lrow][lseg + 8] = *(const uint4*)(Ag + 8);
    *(uint4*)&Bs[0][lrow][lseg]     = *(const uint4*)(Bg);
    *(uint4*)&Bs[0][lrow][lseg + 8] = *(const uint4*)(Bg + 8);
    __syncthreads();

    int buf = 0;
    for (int k0 = 0; k0 < Ev; k0 += 32) {
        uint4 pa0, pa1, pb0, pb1;
        bool more = (k0 + 32 < Ev);
        if (more) {
            pa0 = *(const uint4*)(Ag + k0 + 32);
            pa1 = *(const uint4*)(Ag + k0 + 40);
            pb0 = *(const uint4*)(Bg + k0 + 32);
            pb1 = *(const uint4*)(Bg + k0 + 40);
        }
#pragma unroll
        for (int ks = 0; ks < 4; ks++) {
            int kk = ks * 8 + tg * 2;
            unsigned a0[2], a1[2];
#pragma unroll
            for (int mt = 0; mt < 2; mt++) {
                int row = wm * 32 + mt * 16;
                a0[mt] = *(const unsigned*)&As[buf][row + g][kk];
                a1[mt] = *(const unsigned*)&As[buf][row + 8 + g][kk];
            }
#pragma unroll
            for (int nt = 0; nt < 8; nt++) {
                unsigned b0 = *(const unsigned*)&Bs[buf][wn * 64 + nt * 8 + g][kk];
#pragma unroll
                for (int mt = 0; mt < 2; mt++) MMA_K8(c[mt][nt], a0[mt], a1[mt], b0);
            }
        }
        if (more) {
            *(uint4*)&As[buf ^ 1][lrow][lseg]     = pa0;
            *(uint4*)&As[buf ^ 1][lrow][lseg + 8] = pa1;
            *(uint4*)&Bs[buf ^ 1][lrow][lseg]     = pb0;
            *(uint4*)&Bs[buf ^ 1][lrow][lseg + 8] = pb1;
        }
        __syncthreads();
        buf ^= 1;
    }

#pragma unroll
    for (int nt = 0; nt < 8; nt++) {
        int n = n0 + wn * 64 + nt * 8 + tg * 2;
#pragma unroll
        for (int mt = 0; mt < 2; mt++) {
            int m = m0 + wm * 32 + mt * 16 + g;
            if (m < MEMB)
                *(float2*)&g_gemb[(size_t)m * G4D + n] =
                    make_float2(c[mt][nt][0], c[mt][nt][1]);
            if (m + 8 < MEMB)
                *(float2*)&g_gemb[(size_t)(m + 8) * G4D + n] =
                    make_float2(c[mt][nt][2], c[mt][nt][3]);
        }
    }
}

// ----------------- final batched fc: preds = hall @ fcW.T ----------------------
// A = g_hall16 [2048][512], B = g_fcW16 [10112][512]; grid (16, 79)
__global__ __launch_bounds__(256, 2)
void k_fc_all(const float* __restrict__ bf, float* __restrict__ preds) {
    __shared__ __align__(16) __half As[2][128][40];
    __shared__ __align__(16) __half Bs[2][128][40];
    int m0 = blockIdx.x * 128;
    int n0 = blockIdx.y * 128;
    int tid = threadIdx.x;
    int wid = tid >> 5, lane = tid & 31;
    int wm = wid & 3, wn = wid >> 2;
    int g = lane >> 2, tg = lane & 3;

    int lrow = tid >> 1;
    int lseg = (tid & 1) * 16;

    const __half* Ag = g_hall16 + (size_t)(m0 + lrow) * Dv + lseg;
    const __half* Bg = g_fcW16 + (size_t)(n0 + lrow) * Dv + lseg;

    float c[2][8][4];
#pragma unroll
    for (int mt = 0; mt < 2; mt++)
#pragma unroll
        for (int nt = 0; nt < 8; nt++)
#pragma unroll
            for (int q = 0; q < 4; q++) c[mt][nt][q] = 0.0f;

    *(uint4*)&As[0][lrow][lseg]     = *(const uint4*)(Ag);
    *(uint4*)&As[0][lrow][lseg + 8] = *(const uint4*)(Ag + 8);
    *(uint4*)&Bs[0][lrow][lseg]     = *(const uint4*)(Bg);
    *(uint4*)&Bs[0][lrow][lseg + 8] = *(const uint4*)(Bg + 8);
    __syncthreads();

    int buf = 0;
    for (int k0 = 0; k0 < Dv; k0 += 32) {
        uint4 pa0, pa1, pb0, pb1;
        bool more = (k0 + 32 < Dv);
        if (more) {
            pa0 = *(const uint4*)(Ag + k0 + 32);
            pa1 = *(const uint4*)(Ag + k0 + 40);
            pb0 = *(const uint4*)(Bg + k0 + 32);
            pb1 = *(const uint4*)(Bg + k0 + 40);
        }
#pragma unroll
        for (int ks = 0; ks < 4; ks++) {
            int kk = ks * 8 + tg * 2;
            unsigned a0[2], a1[2];
#pragma unroll
            for (int mt = 0; mt < 2; mt++) {
                int row = wm * 32 + mt * 16;
                a0[mt] = *(const unsigned*)&As[buf][row + g][kk];
                a1[mt] = *(const unsigned*)&As[buf][row + 8 + g][kk];
            }
#pragma unroll
            for (int nt = 0; nt < 8; nt++) {
                unsigned b0 = *(const unsigned*)&Bs[buf][wn * 64 + nt * 8 + g][kk];
#pragma unroll
                for (int mt = 0; mt < 2; mt++) MMA_K8(c[mt][nt], a0[mt], a1[mt], b0);
            }
        }
        if (more) {
            *(uint4*)&As[buf ^ 1][lrow][lseg]     = pa0;
            *(uint4*)&As[buf ^ 1][lrow][lseg + 8] = pa1;
            *(uint4*)&Bs[buf ^ 1][lrow][lseg]     = pb0;
            *(uint4*)&Bs[buf ^ 1][lrow][lseg + 8] = pb1;
        }
        __syncthreads();
        buf ^= 1;
    }

#pragma unroll
    for (int nt = 0; nt < 8; nt++) {
        int n = n0 + wn * 64 + nt * 8 + tg * 2;
        if (n >= Vv) continue;
        float b0f = bf[n], b1f = bf[n + 1];
#pragma unroll
        for (int mt = 0; mt < 2; mt++) {
            int m = m0 + wm * 32 + mt * 16 + g;
            if (m < MEMB) {
                int b = m & 63, t = m >> 6;
                *(float2*)&preds[((size_t)b * Tv + t) * Vv + n] =
                    make_float2(c[mt][nt][0] + b0f, c[mt][nt][1] + b1f);
            }
            int m2 = m + 8;
            if (m2 < MEMB) {
                int b = m2 & 63, t = m2 >> 6;
                *(float2*)&preds[((size_t)b * Tv + t) * Vv + n] =
                    make_float2(c[mt][nt][2] + b0f, c[mt][nt][3] + b1f);
            }
        }
    }
}

// ------------- dh: M=64, K=512 fp16 MMA -> g_dhs (+decb); 4 blocks -------------
__global__ void k_dh16(const float* __restrict__ decb) {
    __shared__ __align__(16) __half As[2][64][40];
    __shared__ __align__(16) __half Bs[2][128][40];
    int n0 = blockIdx.x * 128;
    int tid = threadIdx.x;
    int wid = tid >> 5, lane = tid & 31;
    int wm = wid & 1, wn = wid >> 1;
    int g = lane >> 2, tg = lane & 3;

    int arow = tid >> 2;
    int aseg = (tid & 3) * 8;
    int brow = tid >> 1;
    int bseg = (tid & 1) * 16;

    const __half* Ag = g_xin16 + (size_t)arow * KIN + ENCv + aseg;
    const __half* Bg = g_decW16 + (size_t)(n0 + brow) * Dv + bseg;

    float c[2][4][4];
#pragma unroll
    for (int mt = 0; mt < 2; mt++)
#pragma unroll
        for (int nt = 0; nt < 4; nt++)
#pragma unroll
            for (int q = 0; q < 4; q++) c[mt][nt][q] = 0.0f;

    *(uint4*)&As[0][arow][aseg]     = *(const uint4*)(Ag);
    *(uint4*)&Bs[0][brow][bseg]     = *(const uint4*)(Bg);
    *(uint4*)&Bs[0][brow][bseg + 8] = *(const uint4*)(Bg + 8);
    __syncthreads();

    int buf = 0;
    for (int k0 = 0; k0 < Dv; k0 += 32) {
        uint4 pa, pb0, pb1;
        bool more = (k0 + 32 < Dv);
        if (more) {
            pa  = *(const uint4*)(Ag + k0 + 32);
            pb0 = *(const uint4*)(Bg + k0 + 32);
            pb1 = *(const uint4*)(Bg + k0 + 40);
        }
#pragma unroll
        for (int ks = 0; ks < 4; ks++) {
            int kk = ks * 8 + tg * 2;
            unsigned a0[2], a1[2];
#pragma unroll
            for (int mt = 0; mt < 2; mt++) {
                int row = wm * 32 + mt * 16;
                a0[mt] = *(const unsigned*)&As[buf][row + g][kk];
                a1[mt] = *(const unsigned*)&As[buf][row + 8 + g][kk];
            }
#pragma unroll
            for (int nt = 0; nt < 4; nt++) {
                unsigned b0 = *(const unsigned*)&Bs[buf][wn * 32 + nt * 8 + g][kk];
#pragma unroll
                for (int mt = 0; mt < 2; mt++) MMA_K8(c[mt][nt], a0[mt], a1[mt], b0);
            }
        }
        if (more) {
            *(uint4*)&As[buf ^ 1][arow][aseg]     = pa;
            *(uint4*)&Bs[buf ^ 1][brow][bseg]     = pb0;
            *(uint4*)&Bs[buf ^ 1][brow][bseg + 8] = pb1;
        }
        __syncthreads();
        buf ^= 1;
    }

#pragma unroll
    for (int nt = 0; nt < 4; nt++) {
        int n = n0 + wn * 32 + nt * 8 + tg * 2;
        float b0f = decb[n], b1f = decb[n + 1];
#pragma unroll
        for (int mt = 0; mt < 2; mt++) {
            int m = wm * 32 + mt * 16 + g;
            *(float2*)&g_dhs[m * Av + n] =
                make_float2(c[mt][nt][0] + b0f, c[mt][nt][1] + b1f);
            *(float2*)&g_dhs[(m + 8) * Av + n] =
                make_float2(c[mt][nt][2] + b0f, c[mt][nt][3] + b1f);
        }
    }
}

// ----------------------- e scores: grid (25, 64) -------------------------------
__global__ void k_e(const float* __restrict__ fullW, const float* __restrict__ fullb) {
    __shared__ float s_dh[Av];
    __shared__ float s_fw[Av];
    int b = blockIdx.y;
    int tid = threadIdx.x;
    for (int i = tid; i < Av; i += 256) {
        s_dh[i] = g_dhs[b * Av + i];
        s_fw[i] = fullW[i];
    }
    __syncthreads();
    int w = tid >> 5, lane = tid & 31;
    int p = blockIdx.x * 8 + w;
    if (p >= Pv) return;
    const float* ep = g_enc_proj + (size_t)(b * Pv + p) * Av;
    float acc = 0.0f;
#pragma unroll
    for (int k = lane; k < Av; k += 32) {
        float v = ep[k] + s_dh[k];
        acc += fmaxf(v, 0.0f) * s_fw[k];
    }
    acc = wsum(acc);
    if (!lane) g_e[b * Pv + p] = acc + fullb[0];
}

// ------------- softmax (redundant) + context: grid (4, 64) ---------------------
__global__ void k_ctx(float* __restrict__ out_alphas, int t) {
    __shared__ float red[256];
    __shared__ float s_al[Pv];
    int b = blockIdx.y;
    int tid = threadIdx.x;

    float v = (tid < Pv) ? g_e[b * Pv + tid] : -3.0e38f;
    red[tid] = v; __syncthreads();
    for (int s = 128; s; s >>= 1) {
        if (tid < s) red[tid] = fmaxf(red[tid], red[tid + s]);
        __syncthreads();
    }
    float mx = red[0]; __syncthreads();
    float ex = (tid < Pv) ? expf(v - mx) : 0.0f;
    red[tid] = ex; __syncthreads();
    for (int s = 128; s; s >>= 1) {
        if (tid < s) red[tid] += red[tid + s];
        __syncthreads();
    }
    float inv = 1.0f / red[0];
    if (tid < Pv) {
        float al = ex * inv;
        s_al[tid] = al;
        if (blockIdx.x == 0)
            out_alphas[((size_t)b * Tv + t) * Pv + tid] = al;
    }
    __syncthreads();

    int c = blockIdx.x * 256 + tid;   // half2 column
    const __half2* base2 = (const __half2*)(g_eoT + (size_t)b * Pv * ENCv);
    float ax = 0.f, ay = 0.f;
#pragma unroll 4
    for (int p = 0; p < Pv; p++) {
        float al = s_al[p];
        float2 x = __half22float2(base2[(size_t)p * (ENCv / 2) + c]);
        ax += al * x.x; ay += al * x.y;
    }
    ((__half2*)(g_xin16 + (size_t)b * KIN))[c] = __floats2half2_rn(ax, ay);
}

// ------------------- gates GEMM via HMMA, K-split 4 -----------------------------
__global__ void k_gates_mma() {
    __shared__ __align__(16) __half As[2][64][40];
    __shared__ __align__(16) __half Bs[2][128][40];
    int n0 = blockIdx.x * 128;
    int z = blockIdx.y;
    int kbase = z * GCH;
    int tid = threadIdx.x;
    int wid = tid >> 5, lane = tid & 31;
    int wm = wid & 1, wn = wid >> 1;
    int g = lane >> 2, tg = lane & 3;

    int arow = tid >> 2;
    int aseg = (tid & 3) * 8;
    int brow = tid >> 1;
    int bseg = (tid & 1) * 16;

    const __half* Ag = g_xin16 + (size_t)arow * KIN + kbase + aseg;
    const __half* Bg = g_Wg16 + (size_t)(n0 + brow) * KIN + kbase + bseg;

    float c[2][4][4];
#pragma unroll
    for (int mt = 0; mt < 2; mt++)
#pragma unroll
        for (int nt = 0; nt < 4; nt++)
#pragma unroll
            for (int q = 0; q < 4; q++) c[mt][nt][q] = 0.0f;

    *(uint4*)&As[0][arow][aseg]     = *(const uint4*)(Ag);
    *(uint4*)&Bs[0][brow][bseg]     = *(const uint4*)(Bg);
    *(uint4*)&Bs[0][brow][bseg + 8] = *(const uint4*)(Bg + 8);
    __syncthreads();

    int buf = 0;
    for (int k0 = 0; k0 < GCH; k0 += 32) {
        uint4 pa, pb0, pb1;
        bool more = (k0 + 32 < GCH);
        if (more) {
            pa  = *(const uint4*)(Ag + k0 + 32);
            pb0 = *(const uint4*)(Bg + k0 + 32);
            pb1 = *(const uint4*)(Bg + k0 + 40);
        }
#pragma unroll
        for (int ks = 0; ks < 4; ks++) {
            int kk = ks * 8 + tg * 2;
            unsigned a0[2], a1[2];
#pragma unroll
            for (int mt = 0; mt < 2; mt++) {
                int row = wm * 32 + mt * 16;
                a0[mt] = *(const unsigned*)&As[buf][row + g][kk];
                a1[mt] = *(const unsigned*)&As[buf][row + 8 + g][kk];
            }
#pragma unroll
            for (int nt = 0; nt < 4; nt++) {
                unsigned b0 = *(const unsigned*)&Bs[buf][wn * 32 + nt * 8 + g][kk];
#pragma unroll
                for (int mt = 0; mt < 2; mt++) MMA_K8(c[mt][nt], a0[mt], a1[mt], b0);
            }
        }
        if (more) {
            *(uint4*)&As[buf ^ 1][arow][aseg]     = pa;
            *(uint4*)&Bs[buf ^ 1][brow][bseg]     = pb0;
            *(uint4*)&Bs[buf ^ 1][brow][bseg + 8] = pb1;
        }
        __syncthreads();
        buf ^= 1;
    }

#pragma unroll
    for (int nt = 0; nt < 4; nt++) {
        int n = n0 + wn * 32 + nt * 8 + tg * 2;
#pragma unroll
        for (int mt = 0; mt < 2; mt++) {
            int m = wm * 32 + mt * 16 + g;
            *(float2*)&g_gpart[z][m * G4D + n] = make_float2(c[mt][nt][0], c[mt][nt][1]);
            *(float2*)&g_gpart[z][(m + 8) * G4D + n] = make_float2(c[mt][nt][2], c[mt][nt][3]);
        }
    }
}

// ------------------------------ LSTM pointwise ---------------------------------
__global__ void k_lstm(const float* __restrict__ bih, const float* __restrict__ bhh, int t) {
    int idx = blockIdx.x * blockDim.x + threadIdx.x;
    if (idx >= Bv * Dv) return;
    int b = idx / Dv, d = idx % Dv;
    const float* ge = g_gemb + ((size_t)t * Bv + b) * G4D;
    float gi = bih[d] + bhh[d] + ge[d];
    float gf = bih[Dv + d] + bhh[Dv + d] + ge[Dv + d];
    float gg = bih[2 * Dv + d] + bhh[2 * Dv + d] + ge[2 * Dv + d];
    float go = bih[3 * Dv + d] + bhh[3 * Dv + d] + ge[3 * Dv + d];
    int base = b * G4D + d;
#pragma unroll
    for (int z = 0; z < GZ; z++) {
        gi += g_gpart[z][base];
        gf += g_gpart[z][base + Dv];
        gg += g_gpart[z][base + 2 * Dv];
        go += g_gpart[z][base + 3 * Dv];
    }
    float c = g_c[idx];
    float cn = sigm(gf) * c + sigm(gi) * tanhf(gg);
    float hn = sigm(go) * tanhf(cn);
    g_c[idx] = cn;
    g_h[idx] = hn;
    __half h16 = __float2half(hn);
    g_xin16[b * KIN + ENCv + d] = h16;
    g_hall16[((size_t)t * Bv + b) * Dv + d] = h16;   // history for batched fc
}

// --------------------------------- launcher ------------------------------------
extern "C" void kernel_launch(void* const* d_in, const int* in_sizes, int n_in,
                              void* d_out, int out_size) {
    const float* eo    = (const float*)d_in[0];
    const int*   caps  = (const int*)d_in[1];
    const float* emb   = (const float*)d_in[3];
    const float* encW  = (const float*)d_in[4];
    const float* encb  = (const float*)d_in[5];
    const float* decW  = (const float*)d_in[6];
    const float* decb  = (const float*)d_in[7];
    const float* fullW = (const float*)d_in[8];
    const float* fullb = (const float*)d_in[9];
    const float* ihW   = (const float*)d_in[10];
    const float* ihb   = (const float*)d_in[11];
    const float* icW   = (const float*)d_in[12];
    const float* icb   = (const float*)d_in[13];
    const float* Wih   = (const float*)d_in[14];
    const float* bih   = (const float*)d_in[15];
    const float* Whh   = (const float*)d_in[16];
    const float* bhh   = (const float*)d_in[17];
    const float* fcW   = (const float*)d_in[18];
    const float* fcb   = (const float*)d_in[19];

    float* preds  = (float*)d_out;
    float* alphas = preds + (size_t)Bv * Tv * Vv;

    k_zero_tail<<<(Bv * Vv + Bv * Pv + Bv * ENCv + 255) / 256, 256>>>(preds, alphas);
    k_cvtT<<<dim3(ENCv / 32, (Pv + 31) / 32, Bv), dim3(32, 8)>>>(eo);
    k_cvtW<<<(Av * ENCv / 4 + 255) / 256, 256>>>(encW);
    k_cvt_Wg<<<(G4D * KIN / 2 + 255) / 256, 256>>>(Wih, Whh);
    k_cvt_fcW<<<(NFCPAD * Dv / 2 + 255) / 256, 256>>>(fcW);
    k_cvt_decW<<<(Av * Dv / 2 + 255) / 256, 256>>>(decW);
    k_cvt_emb<<<(2048 * Ev / 2 + 255) / 256, 256>>>(caps, emb);
    k_cvt_Wihe<<<(G4D * Ev / 2 + 255) / 256, 256>>>(Wih);
    k_init<<<(2 * Bv * Dv * 32 + 255) / 256, 256>>>(ihW, ihb, icW, icb);
    k_embW_mma<<<dim3(16, 16), 256>>>();
    k_encproj_mma<<<dim3(98, 4), 256>>>(encb);
    k_dh16<<<4, 256>>>(decb);

    for (int t = 0; t < NSTEP; t++) {
        k_e<<<dim3(25, Bv), 256>>>(fullW, fullb);
        k_ctx<<<dim3(4, Bv), 256>>>(alphas, t);
        k_gates_mma<<<dim3(16, GZ), 256>>>();
        k_lstm<<<(Bv * Dv + 255) / 256, 256>>>(bih, bhh, t);
        if (t + 1 < NSTEP) k_dh16<<<4, 256>>>(decb);
    }
    k_fc_all<<<dim3(16, 79), 256>>>(fcb, preds);
}